// round 11
// baseline (speedup 1.0000x reference)
#include <cuda_runtime.h>
#include <cuda_bf16.h>
#include <cuda_fp16.h>
#include <cstdint>
#include <stdint.h>
#include <math.h>

#define NTOK   4096      // B*S
#define HID    2048
#define NH     16
#define HD     128
#define MLPD   8192
#define SEQL   2048

// ------------------------- persistent device scratch -------------------------
__device__ __nv_bfloat16 g_wqkv[3 * HID * HID];   // concat q|k|v weights
__device__ __nv_bfloat16 g_wo[HID * HID];
__device__ __nv_bfloat16 g_wgu[2 * MLPD * HID];   // concat gate|up weights
__device__ __nv_bfloat16 g_wd[HID * MLPD];
__device__ float g_sqkv[3 * HID], g_so[HID];
__device__ float g_sgu[2 * MLPD], g_sd[HID];

__device__ __nv_bfloat16 g_aq[NTOK * MLPD];   // quantized activations (bf16 ints)
__device__ float g_as[NTOK];                  // per-token activation scales
__device__ __half g_qh[NTOK * HID];           // q fp16, [B,H,S,D] (roped in place)
__device__ __half g_kh[NTOK * HID];           // k fp16, [B,H,S,D] (roped in place)
__device__ __half g_vh[NTOK * HID];           // v fp16, [B,H,S,D]
__device__ float g_attno[NTOK * HID];         // attention output, [T, H*D]
__device__ float g_x1[NTOK * HID];            // residual after attention
__device__ __half g_guh[NTOK * 2 * MLPD];     // [gate|up] fp16, row stride 16384

// ------------------------- weight quantization (one-pass, bf16 out) -------------------------
__global__ void quant_w_kernel(const float* __restrict__ W,
                               const float* __restrict__ alpha,
                               __nv_bfloat16* __restrict__ Wq,
                               float* __restrict__ rs, int K) {
    int o = blockIdx.x;
    const float4* row = (const float4*)(W + (size_t)o * K);
    const int nt = K >> 10;              // float4s per thread (2 for K=2048, 8 for K=8192)
    float4 v[8];
    float s = 0.f;
#pragma unroll
    for (int i = 0; i < 8; i++) {
        if (i < nt) {
            v[i] = row[i * 256 + threadIdx.x];
            s += fabsf(v[i].x) + fabsf(v[i].y) + fabsf(v[i].z) + fabsf(v[i].w);
        }
    }
    __shared__ float red[256];
    red[threadIdx.x] = s;
    __syncthreads();
    for (int st = 128; st > 0; st >>= 1) {
        if (threadIdx.x < st) red[threadIdx.x] += red[threadIdx.x + st];
        __syncthreads();
    }
    float wsc = red[0] / (float)K + 1e-8f;
    if (threadIdx.x == 0) rs[o] = wsc * alpha[o] / 127.0f;
    __nv_bfloat162* orow = (__nv_bfloat162*)(Wq + (size_t)o * K);
#pragma unroll
    for (int i = 0; i < 8; i++) {
        if (i < nt) {
            int idx = i * 256 + threadIdx.x;
            float q0 = fminf(fmaxf(rintf(v[i].x / wsc), -1.f), 1.f);
            float q1 = fminf(fmaxf(rintf(v[i].y / wsc), -1.f), 1.f);
            float q2 = fminf(fmaxf(rintf(v[i].z / wsc), -1.f), 1.f);
            float q3 = fminf(fmaxf(rintf(v[i].w / wsc), -1.f), 1.f);
            orow[idx * 2 + 0] = __floats2bfloat162_rn(q0, q1);
            orow[idx * 2 + 1] = __floats2bfloat162_rn(q2, q3);
        }
    }
}

// ------------------------- rmsnorm + activation quant (N = 2048, bf16 out) -------------------------
__global__ void rms_quant_kernel(const float* __restrict__ x,
                                 const float* __restrict__ w,
                                 __nv_bfloat16* __restrict__ aq,
                                 float* __restrict__ as_) {
    int t = blockIdx.x;
    const float* row = x + (size_t)t * HID;
    float v[8], h[8];
    float ss = 0.f;
#pragma unroll
    for (int j = 0; j < 8; j++) {
        v[j] = row[j * 256 + threadIdx.x];
        ss += v[j] * v[j];
    }
    __shared__ float red[256];
    red[threadIdx.x] = ss;
    __syncthreads();
    for (int st = 128; st > 0; st >>= 1) {
        if (threadIdx.x < st) red[threadIdx.x] += red[threadIdx.x + st];
        __syncthreads();
    }
    float rms = sqrtf(red[0] / (float)HID + 1e-6f);
    __syncthreads();
    float mx = 0.f;
#pragma unroll
    for (int j = 0; j < 8; j++) {
        h[j] = v[j] / rms * w[j * 256 + threadIdx.x];
        mx = fmaxf(mx, fabsf(h[j]));
    }
    red[threadIdx.x] = mx;
    __syncthreads();
    for (int st = 128; st > 0; st >>= 1) {
        if (threadIdx.x < st) red[threadIdx.x] = fmaxf(red[threadIdx.x], red[threadIdx.x + st]);
        __syncthreads();
    }
    float asc = red[0] + 1e-8f;
    if (threadIdx.x == 0) as_[t] = asc;
    __nv_bfloat16* orow = aq + (size_t)t * HID;
#pragma unroll
    for (int j = 0; j < 8; j++) {
        float q = h[j] / asc * 127.0f;
        q = fminf(fmaxf(q, -128.f), 127.f);
        orow[j * 256 + threadIdx.x] = __float2bfloat16(rintf(q));
    }
}

// ------------------------- plain activation quant (N = 2048, bf16 out) -------------------------
__global__ void act_quant_kernel(const float* __restrict__ x,
                                 __nv_bfloat16* __restrict__ aq,
                                 float* __restrict__ as_, int N) {
    int t = blockIdx.x;
    const float* row = x + (size_t)t * N;
    __shared__ float red[256];
    float mx = 0.f;
    for (int i = threadIdx.x; i < N; i += 256) mx = fmaxf(mx, fabsf(row[i]));
    red[threadIdx.x] = mx;
    __syncthreads();
    for (int st = 128; st > 0; st >>= 1) {
        if (threadIdx.x < st) red[threadIdx.x] = fmaxf(red[threadIdx.x], red[threadIdx.x + st]);
        __syncthreads();
    }
    float asc = red[0] + 1e-8f;
    if (threadIdx.x == 0) as_[t] = asc;
    __nv_bfloat16* orow = aq + (size_t)t * N;
    for (int i = threadIdx.x; i < N; i += 256) {
        float q = row[i] / asc * 127.0f;
        q = fminf(fmaxf(q, -128.f), 127.f);
        orow[i] = __float2bfloat16(rintf(q));
    }
}

// ------------------------- fused silu*up + quant (row = [gate(8192)|up(8192)] fp16) -------------------------
__global__ void __launch_bounds__(512)
silu_quant_kernel(const __half* __restrict__ gu,
                  __nv_bfloat16* __restrict__ aq, float* __restrict__ as_) {
    int t = blockIdx.x;
    const __half2* rg = (const __half2*)(gu + (size_t)t * 2 * MLPD);
    const __half2* ru = (const __half2*)(gu + (size_t)t * 2 * MLPD + MLPD);
    float v[16];
    float mx = 0.f;
#pragma unroll
    for (int j = 0; j < 8; j++) {
        int idx = j * 512 + threadIdx.x;
        float2 gx = __half22float2(rg[idx]);
        float2 ux = __half22float2(ru[idx]);
        float y0 = gx.x / (1.0f + __expf(-gx.x)) * ux.x;
        float y1 = gx.y / (1.0f + __expf(-gx.y)) * ux.y;
        v[j * 2] = y0; v[j * 2 + 1] = y1;
        mx = fmaxf(mx, fmaxf(fabsf(y0), fabsf(y1)));
    }
    __shared__ float red[512];
    red[threadIdx.x] = mx;
    __syncthreads();
    for (int st = 256; st > 0; st >>= 1) {
        if (threadIdx.x < st) red[threadIdx.x] = fmaxf(red[threadIdx.x], red[threadIdx.x + st]);
        __syncthreads();
    }
    float asc = red[0] + 1e-8f;
    if (threadIdx.x == 0) as_[t] = asc;
    __nv_bfloat162* orow = (__nv_bfloat162*)(aq + (size_t)t * MLPD);
#pragma unroll
    for (int j = 0; j < 8; j++) {
        int idx = j * 512 + threadIdx.x;
        float q0 = rintf(fminf(fmaxf(v[j * 2] / asc * 127.0f, -128.f), 127.f));
        float q1 = rintf(fminf(fmaxf(v[j * 2 + 1] / asc * 127.0f, -128.f), 127.f));
        orow[idx] = __floats2bfloat162_rn(q0, q1);
    }
}

// ------------------------- mma helpers -------------------------
__device__ __forceinline__ unsigned smem_addr(const void* p) {
    return (unsigned)__cvta_generic_to_shared(p);
}
__device__ __forceinline__ void cp_async16(void* dst, const void* src) {
    asm volatile("cp.async.cg.shared.global [%0], [%1], 16;\n"
                 :: "r"(smem_addr(dst)), "l"(src));
}
__device__ __forceinline__ void cp_commit() { asm volatile("cp.async.commit_group;\n"); }
__device__ __forceinline__ void ldm4(unsigned* r, unsigned addr) {
    asm volatile("ldmatrix.sync.aligned.m8n8.x4.shared.b16 {%0,%1,%2,%3}, [%4];\n"
                 : "=r"(r[0]), "=r"(r[1]), "=r"(r[2]), "=r"(r[3]) : "r"(addr));
}
__device__ __forceinline__ void ldm4t(unsigned* r, unsigned addr) {
    asm volatile("ldmatrix.sync.aligned.m8n8.x4.trans.shared.b16 {%0,%1,%2,%3}, [%4];\n"
                 : "=r"(r[0]), "=r"(r[1]), "=r"(r[2]), "=r"(r[3]) : "r"(addr));
}
__device__ __forceinline__ void mma16816(float* c, const unsigned* a, unsigned b0, unsigned b1) {
    asm volatile(
        "mma.sync.aligned.m16n8k16.row.col.f32.bf16.bf16.f32 "
        "{%0,%1,%2,%3},{%4,%5,%6,%7},{%8,%9},{%0,%1,%2,%3};\n"
        : "+f"(c[0]), "+f"(c[1]), "+f"(c[2]), "+f"(c[3])
        : "r"(a[0]), "r"(a[1]), "r"(a[2]), "r"(a[3]), "r"(b0), "r"(b1));
}
__device__ __forceinline__ void mma16816h(float* c, const unsigned* a, unsigned b0, unsigned b1) {
    asm volatile(
        "mma.sync.aligned.m16n8k16.row.col.f32.f16.f16.f32 "
        "{%0,%1,%2,%3},{%4,%5,%6,%7},{%8,%9},{%0,%1,%2,%3};\n"
        : "+f"(c[0]), "+f"(c[1]), "+f"(c[2]), "+f"(c[3])
        : "r"(a[0]), "r"(a[1]), "r"(a[2]), "r"(a[3]), "r"(b0), "r"(b1));
}
__device__ __forceinline__ unsigned packh2(float a, float b) {
    __half2 h = __floats2half2_rn(a, b);
    return *reinterpret_cast<unsigned*>(&h);
}

// ------------------------- bf16 tensor-core GEMM (validated mainloop) -------------------------
// MODE 1: fp16 C0[t*N+o]
// MODE 2: QKV — fp16 at [B,H,S,D]; buffer chosen from col block (C0=q, C1=k, C2=v)
// MODE 3: fp32 C0[t*N+o] = val + res[t*N+o]
#define BM 128
#define BN 128
#define BK 64
__device__ __forceinline__ int sw_off(int row, int u) {
    return (row * 8 + (u ^ (row & 7))) * 8;
}
__device__ __forceinline__ size_t vaddr(int t, int o) {
    return ((size_t)((t >> 11) * NH + (o >> 7)) * SEQL + (t & (SEQL - 1))) * HD + (o & (HD - 1));
}

template <int MODE>
__global__ void __launch_bounds__(256)
gemm_bf16_kernel(const __nv_bfloat16* __restrict__ A, const __nv_bfloat16* __restrict__ B,
                 const float* __restrict__ rs, const float* __restrict__ asc,
                 void* __restrict__ C0, void* __restrict__ C1, void* __restrict__ C2,
                 const float* __restrict__ res, int K, int N) {
    extern __shared__ __nv_bfloat16 sm[];
    __nv_bfloat16* As = sm;
    __nv_bfloat16* Bs = sm + 2 * BM * BK;

    const int tid = threadIdx.x;
    const int lane = tid & 31;
    const int wid = tid >> 5;
    const int warp_m = wid >> 1;
    const int warp_n = wid & 1;
    const int rowBase = blockIdx.y * BM;
    const int colBase = blockIdx.x * BN;

    float acc[2][8][4];
#pragma unroll
    for (int mt = 0; mt < 2; mt++)
#pragma unroll
        for (int nt = 0; nt < 8; nt++)
#pragma unroll
            for (int i = 0; i < 4; i++) acc[mt][nt][i] = 0.f;

    const int nsteps = K / BK;
    {
#pragma unroll
        for (int it = 0; it < 4; it++) {
            int j = tid + it * 256;
            int row = j >> 3, u = j & 7;
            cp_async16(As + sw_off(row, u), A + (size_t)(rowBase + row) * K + u * 8);
            cp_async16(Bs + sw_off(row, u), B + (size_t)(colBase + row) * K + u * 8);
        }
        cp_commit();
    }

    for (int s = 0; s < nsteps; s++) {
        if (s + 1 < nsteps) {
            __nv_bfloat16* Ab = As + ((s + 1) & 1) * BM * BK;
            __nv_bfloat16* Bb = Bs + ((s + 1) & 1) * BN * BK;
            int k0 = (s + 1) * BK;
#pragma unroll
            for (int it = 0; it < 4; it++) {
                int j = tid + it * 256;
                int row = j >> 3, u = j & 7;
                cp_async16(Ab + sw_off(row, u), A + (size_t)(rowBase + row) * K + k0 + u * 8);
                cp_async16(Bb + sw_off(row, u), B + (size_t)(colBase + row) * K + k0 + u * 8);
            }
            cp_commit();
            asm volatile("cp.async.wait_group 1;\n");
        } else {
            asm volatile("cp.async.wait_group 0;\n");
        }
        __syncthreads();

        const __nv_bfloat16* Ab = As + (s & 1) * BM * BK;
        const __nv_bfloat16* Bb = Bs + (s & 1) * BN * BK;
        const unsigned a_base = smem_addr(Ab);
        const unsigned b_base = smem_addr(Bb);

#pragma unroll
        for (int kc = 0; kc < 4; kc++) {
            const int u = kc * 2 + (lane >> 4);
            unsigned afrag[2][4];
#pragma unroll
            for (int mt = 0; mt < 2; mt++) {
                int row = warp_m * 32 + mt * 16 + (lane & 15);
                ldm4(afrag[mt], a_base + (unsigned)sw_off(row, u) * 2);
            }
            unsigned bfrag[8][2];
#pragma unroll
            for (int np = 0; np < 4; np++) {
                int row = warp_n * 64 + np * 16 + (lane & 15);
                unsigned r[4];
                ldm4(r, b_base + (unsigned)sw_off(row, u) * 2);
                bfrag[np * 2 + 0][0] = r[0]; bfrag[np * 2 + 0][1] = r[2];
                bfrag[np * 2 + 1][0] = r[1]; bfrag[np * 2 + 1][1] = r[3];
            }
#pragma unroll
            for (int mt = 0; mt < 2; mt++)
#pragma unroll
                for (int nt = 0; nt < 8; nt++)
                    mma16816(acc[mt][nt], afrag[mt], bfrag[nt][0], bfrag[nt][1]);
        }
        __syncthreads();
    }

    // select QKV output buffer (uniform per block: BN=128 << 2048 span)
    __half* Csel = nullptr;
    int cshift = 0;
    if (MODE == 2) {
        int which = colBase >> 11;
        Csel = (which == 0) ? (__half*)C0 : (which == 1) ? (__half*)C1 : (__half*)C2;
        cshift = which << 11;
    }

#pragma unroll
    for (int mt = 0; mt < 2; mt++) {
        int r0 = rowBase + warp_m * 32 + mt * 16 + (lane >> 2);
        float sA = asc[r0], sB = asc[r0 + 8];
#pragma unroll
        for (int nt = 0; nt < 8; nt++) {
            int c0 = colBase + warp_n * 64 + nt * 8 + (lane & 3) * 2;
            float rs0 = rs[c0], rs1 = rs[c0 + 1];
            float v00 = acc[mt][nt][0] * rs0 * sA;
            float v01 = acc[mt][nt][1] * rs1 * sA;
            float v10 = acc[mt][nt][2] * rs0 * sB;
            float v11 = acc[mt][nt][3] * rs1 * sB;
            if (MODE == 1) {
                __half2* C = (__half2*)C0;
                C[((size_t)r0 * N + c0) >> 1]       = __floats2half2_rn(v00, v01);
                C[((size_t)(r0 + 8) * N + c0) >> 1] = __floats2half2_rn(v10, v11);
            } else if (MODE == 2) {
                int oc = c0 - cshift;
                *(__half2*)(Csel + vaddr(r0, oc))     = __floats2half2_rn(v00, v01);
                *(__half2*)(Csel + vaddr(r0 + 8, oc)) = __floats2half2_rn(v10, v11);
            } else {
                float* C = (float*)C0;
                C[(size_t)r0 * N + c0]           = v00 + res[(size_t)r0 * N + c0];
                C[(size_t)r0 * N + c0 + 1]       = v01 + res[(size_t)r0 * N + c0 + 1];
                C[(size_t)(r0 + 8) * N + c0]     = v10 + res[(size_t)(r0 + 8) * N + c0];
                C[(size_t)(r0 + 8) * N + c0 + 1] = v11 + res[(size_t)(r0 + 8) * N + c0 + 1];
            }
        }
    }
}

// ------------------------- in-place RoPE on fp16 q,k in [B,H,S,D] -------------------------
__global__ void rope_inplace_kernel(__half* __restrict__ q, __half* __restrict__ k) {
    int idx = blockIdx.x * blockDim.x + threadIdx.x;
    if (idx >= NTOK * NH * 64) return;
    int d = idx & 63;
    int row = idx >> 6;                 // bh*SEQL + s
    int s = row & (SEQL - 1);
    float invf = 1.0f / powf(10000.0f, (float)d / 64.0f);
    float ang = (float)s * invf;
    float sn, c;
    sincosf(ang, &sn, &c);
    size_t base = (size_t)row * HD;
    float x1 = __half2float(q[base + d]), x2 = __half2float(q[base + d + 64]);
    q[base + d]      = __float2half(x1 * c - x2 * sn);
    q[base + d + 64] = __float2half(x2 * c + x1 * sn);
    float y1 = __half2float(k[base + d]), y2 = __half2float(k[base + d + 64]);
    k[base + d]      = __float2half(y1 * c - y2 * sn);
    k[base + d + 64] = __float2half(y2 * c + y1 * sn);
}

// ------------------------- fp16 mma flash attention (validated) -------------------------
__device__ __forceinline__ int sw16(int row, int u) {
    return row * 128 + (((u ^ row) & 7) | (u & 8)) * 8;
}

__device__ __forceinline__ void attn_load_tile(__half* Ks, __half* Vs,
                                               const __half* kb_, const __half* vb_,
                                               int tid) {
#pragma unroll
    for (int it = 0; it < 8; it++) {
        int idx = tid + it * 128;
        int row = idx >> 4, u = idx & 15;
        cp_async16(Ks + sw16(row, u), kb_ + (size_t)row * HD + u * 8);
        cp_async16(Vs + sw16(row, u), vb_ + (size_t)row * HD + u * 8);
    }
}

__global__ void __launch_bounds__(128)
attn_mma_kernel(const __half* __restrict__ qh, const __half* __restrict__ kh,
                const __half* __restrict__ vh, const int* __restrict__ mask,
                float* __restrict__ out) {
    extern __shared__ __half ash[];
    __half* Qs = ash;
    __half* KsA[2] = {ash + 8192, ash + 16384};
    __half* VsA[2] = {ash + 24576, ash + 32768};

    const int tid = threadIdx.x;
    const int lane = tid & 31;
    const int wid = tid >> 5;
    const int bx = blockIdx.x;
    const int bh = bx & 31;
    const int qslot = bx >> 5;
    const int qb = (31 - qslot) * 64;
    const int b = bh >> 4;
    const int h = bh & 15;

    const __half* qbase = qh + ((size_t)bh * SEQL + qb) * HD;
    const __half* kbase = kh + (size_t)bh * SEQL * HD;
    const __half* vbase = vh + (size_t)bh * SEQL * HD;
    const int* mrow = mask + b * SEQL;
    const int ntiles = qb / 64 + 1;

#pragma unroll
    for (int it = 0; it < 8; it++) {
        int idx = tid + it * 128;
        int row = idx >> 4, u = idx & 15;
        cp_async16(Qs + sw16(row, u), qbase + (size_t)row * HD + u * 8);
    }
    attn_load_tile(KsA[0], VsA[0], kbase, vbase, tid);
    cp_commit();
    if (ntiles > 1) attn_load_tile(KsA[1], VsA[1], kbase + 64 * HD, vbase + 64 * HD, tid);
    cp_commit();

    float oacc[16][4];
#pragma unroll
    for (int i = 0; i < 16; i++) { oacc[i][0] = oacc[i][1] = oacc[i][2] = oacc[i][3] = 0.f; }
    float m0 = -1e30f, m1 = -1e30f, l0 = 0.f, l1 = 0.f;
    const float scale = 0.08838834764831845f;
    const int r = lane >> 2;
    const int c2 = (lane & 3) * 2;
    const int qr0 = qb + wid * 16 + r;
    const unsigned qs_base = smem_addr(Qs);

    for (int t = 0; t < ntiles; t++) {
        asm volatile("cp.async.wait_group 1;\n");
        __syncthreads();
        const int kb = t * 64;
        const unsigned k_base = smem_addr(KsA[t & 1]);
        const unsigned v_base = smem_addr(VsA[t & 1]);

        float sacc[8][4];
#pragma unroll
        for (int nt = 0; nt < 8; nt++) { sacc[nt][0] = sacc[nt][1] = sacc[nt][2] = sacc[nt][3] = 0.f; }
#pragma unroll
        for (int kc = 0; kc < 8; kc++) {
            const int u = kc * 2 + (lane >> 4);
            unsigned afrag[4];
            ldm4(afrag, qs_base + (unsigned)sw16(wid * 16 + (lane & 15), u) * 2);
#pragma unroll
            for (int np = 0; np < 4; np++) {
                unsigned rr[4];
                ldm4(rr, k_base + (unsigned)sw16(np * 16 + (lane & 15), u) * 2);
                mma16816h(sacc[np * 2 + 0], afrag, rr[0], rr[2]);
                mma16816h(sacc[np * 2 + 1], afrag, rr[1], rr[3]);
            }
        }

        float mx0 = -1e30f, mx1 = -1e30f;
#pragma unroll
        for (int nt = 0; nt < 8; nt++) {
#pragma unroll
            for (int i = 0; i < 4; i++) {
                int col = kb + nt * 8 + c2 + (i & 1);
                int qr = qr0 + ((i >> 1) << 3);
                float s = sacc[nt][i] * scale;
                bool dead = (col > qr) || (mrow[col] == 0);
                s = dead ? -10000.f : fmaxf(s, -10000.f);
                sacc[nt][i] = s;
                if (i < 2) mx0 = fmaxf(mx0, s); else mx1 = fmaxf(mx1, s);
            }
        }
        mx0 = fmaxf(mx0, __shfl_xor_sync(0xffffffffu, mx0, 1));
        mx0 = fmaxf(mx0, __shfl_xor_sync(0xffffffffu, mx0, 2));
        mx1 = fmaxf(mx1, __shfl_xor_sync(0xffffffffu, mx1, 1));
        mx1 = fmaxf(mx1, __shfl_xor_sync(0xffffffffu, mx1, 2));
        float nm0 = fmaxf(m0, mx0), nm1 = fmaxf(m1, mx1);
        float cor0 = __expf(m0 - nm0), cor1 = __expf(m1 - nm1);
        float ls0 = 0.f, ls1 = 0.f;
#pragma unroll
        for (int nt = 0; nt < 8; nt++) {
#pragma unroll
            for (int i = 0; i < 4; i++) {
                float p = __expf(sacc[nt][i] - ((i < 2) ? nm0 : nm1));
                sacc[nt][i] = p;
                if (i < 2) ls0 += p; else ls1 += p;
            }
        }
        ls0 += __shfl_xor_sync(0xffffffffu, ls0, 1);
        ls0 += __shfl_xor_sync(0xffffffffu, ls0, 2);
        ls1 += __shfl_xor_sync(0xffffffffu, ls1, 1);
        ls1 += __shfl_xor_sync(0xffffffffu, ls1, 2);
        l0 = l0 * cor0 + ls0;
        l1 = l1 * cor1 + ls1;
        m0 = nm0; m1 = nm1;
#pragma unroll
        for (int i = 0; i < 16; i++) {
            oacc[i][0] *= cor0; oacc[i][1] *= cor0;
            oacc[i][2] *= cor1; oacc[i][3] *= cor1;
        }

#pragma unroll
        for (int kc2 = 0; kc2 < 4; kc2++) {
            unsigned pa[4];
            pa[0] = packh2(sacc[2 * kc2][0], sacc[2 * kc2][1]);
            pa[1] = packh2(sacc[2 * kc2][2], sacc[2 * kc2][3]);
            pa[2] = packh2(sacc[2 * kc2 + 1][0], sacc[2 * kc2 + 1][1]);
            pa[3] = packh2(sacc[2 * kc2 + 1][2], sacc[2 * kc2 + 1][3]);
#pragma unroll
            for (int dnp = 0; dnp < 8; dnp++) {
                unsigned rr[4];
                ldm4t(rr, v_base + (unsigned)sw16(kc2 * 16 + (lane & 15), dnp * 2 + (lane >> 4)) * 2);
                mma16816h(oacc[dnp * 2 + 0], pa, rr[0], rr[1]);
                mma16816h(oacc[dnp * 2 + 1], pa, rr[2], rr[3]);
            }
        }
        __syncthreads();
        if (t + 2 < ntiles)
            attn_load_tile(KsA[t & 1], VsA[t & 1], kbase + (size_t)(t + 2) * 64 * HD,
                           vbase + (size_t)(t + 2) * 64 * HD, tid);
        cp_commit();
    }

    float inv0 = 1.f / l0, inv1 = 1.f / l1;
    size_t o0 = ((size_t)b * SEQL + qr0) * HID + h * HD;
    size_t o1 = o0 + 8 * HID;
#pragma unroll
    for (int dnt = 0; dnt < 16; dnt++) {
        int d = dnt * 8 + c2;
        float2 v0 = make_float2(oacc[dnt][0] * inv0, oacc[dnt][1] * inv0);
        float2 v1 = make_float2(oacc[dnt][2] * inv1, oacc[dnt][3] * inv1);
        *(float2*)(out + o0 + d) = v0;
        *(float2*)(out + o1 + d) = v1;
    }
}

// ------------------------- host orchestration -------------------------
extern "C" void kernel_launch(void* const* d_in, const int* in_sizes, int n_in,
                              void* d_out, int out_size) {
    const float* x     = (const float*)d_in[0];
    const int*   amask = (const int*)d_in[1];
    const float* wq = (const float*)d_in[2];   const float* aq_a = (const float*)d_in[3];
    const float* wk = (const float*)d_in[4];   const float* ak_a = (const float*)d_in[5];
    const float* wv = (const float*)d_in[6];   const float* av_a = (const float*)d_in[7];
    const float* wo = (const float*)d_in[8];   const float* ao_a = (const float*)d_in[9];
    const float* wg = (const float*)d_in[10];  const float* ag_a = (const float*)d_in[11];
    const float* wu = (const float*)d_in[12];  const float* au_a = (const float*)d_in[13];
    const float* wd = (const float*)d_in[14];  const float* ad_a = (const float*)d_in[15];
    const float* n1 = (const float*)d_in[16];
    const float* n2 = (const float*)d_in[17];
    float* out = (float*)d_out;

    __nv_bfloat16 *p_wqkv, *p_wo, *p_wgu, *p_wd, *p_aq;
    __half *p_qh, *p_kh, *p_vh, *p_guh;
    float *p_sqkv, *p_so, *p_sgu, *p_sd;
    float *p_as, *p_attno, *p_x1;
    cudaGetSymbolAddress((void**)&p_wqkv, g_wqkv);
    cudaGetSymbolAddress((void**)&p_wo, g_wo);
    cudaGetSymbolAddress((void**)&p_wgu, g_wgu);
    cudaGetSymbolAddress((void**)&p_wd, g_wd);
    cudaGetSymbolAddress((void**)&p_sqkv, g_sqkv);
    cudaGetSymbolAddress((void**)&p_so, g_so);
    cudaGetSymbolAddress((void**)&p_sgu, g_sgu);
    cudaGetSymbolAddress((void**)&p_sd, g_sd);
    cudaGetSymbolAddress((void**)&p_aq, g_aq);
    cudaGetSymbolAddress((void**)&p_as, g_as);
    cudaGetSymbolAddress((void**)&p_qh, g_qh);
    cudaGetSymbolAddress((void**)&p_kh, g_kh);
    cudaGetSymbolAddress((void**)&p_vh, g_vh);
    cudaGetSymbolAddress((void**)&p_attno, g_attno);
    cudaGetSymbolAddress((void**)&p_x1, g_x1);
    cudaGetSymbolAddress((void**)&p_guh, g_guh);

    const int smem_bytes = 2 * (BM * BK + BN * BK) * 2;   // 65536
    cudaFuncSetAttribute(gemm_bf16_kernel<1>, cudaFuncAttributeMaxDynamicSharedMemorySize, smem_bytes);
    cudaFuncSetAttribute(gemm_bf16_kernel<2>, cudaFuncAttributeMaxDynamicSharedMemorySize, smem_bytes);
    cudaFuncSetAttribute(gemm_bf16_kernel<3>, cudaFuncAttributeMaxDynamicSharedMemorySize, smem_bytes);
    const int attn_smem = 40960 * 2;                      // 81920
    cudaFuncSetAttribute(attn_mma_kernel, cudaFuncAttributeMaxDynamicSharedMemorySize, attn_smem);

    // 1) quantize all weights into concatenated buffers
    quant_w_kernel<<<HID, 256>>>(wq, aq_a, p_wqkv,                          p_sqkv,            HID);
    quant_w_kernel<<<HID, 256>>>(wk, ak_a, p_wqkv + (size_t)HID * HID,      p_sqkv + HID,      HID);
    quant_w_kernel<<<HID, 256>>>(wv, av_a, p_wqkv + 2 * (size_t)HID * HID,  p_sqkv + 2 * HID,  HID);
    quant_w_kernel<<<HID, 256>>>(wo, ao_a, p_wo, p_so, HID);
    quant_w_kernel<<<MLPD, 256>>>(wg, ag_a, p_wgu,                          p_sgu,             HID);
    quant_w_kernel<<<MLPD, 256>>>(wu, au_a, p_wgu + (size_t)MLPD * HID,     p_sgu + MLPD,      HID);
    quant_w_kernel<<<HID, 256>>>(wd, ad_a, p_wd, p_sd, MLPD);

    // 2) rmsnorm + quantize input
    rms_quant_kernel<<<NTOK, 256>>>(x, n1, p_aq, p_as);

    // 3) fused QKV projection -> fp16 [B,H,S,D]
    dim3 gqkv(3 * HID / BN, NTOK / BM);
    gemm_bf16_kernel<2><<<gqkv, 256, smem_bytes>>>(p_aq, p_wqkv, p_sqkv, p_as,
                                                   p_qh, p_kh, p_vh, nullptr, HID, HID);

    // 4) in-place rope on q,k
    rope_inplace_kernel<<<(NTOK * NH * 64 + 255) / 256, 256>>>(p_qh, p_kh);

    // 5) mma flash attention
    attn_mma_kernel<<<(SEQL / 64) * 32, 128, attn_smem>>>(p_qh, p_kh, p_vh, amask, p_attno);

    // 6) output projection with fused residual: x1 = x + attno @ wo
    act_quant_kernel<<<NTOK, 256>>>(p_attno, p_aq, p_as, HID);
    dim3 g16(HID / BN, NTOK / BM);
    gemm_bf16_kernel<3><<<g16, 256, smem_bytes>>>(p_aq, p_wo, p_so, p_as,
                                                  p_x1, nullptr, nullptr, x, HID, HID);

    // 7) rmsnorm + quant of x1
    rms_quant_kernel<<<NTOK, 256>>>(p_x1, n2, p_aq, p_as);

    // 8) MLP: fused gate|up GEMM -> fp16, silu+quant, down GEMM with residual into d_out
    dim3 ggu(2 * MLPD / BN, NTOK / BM);
    gemm_bf16_kernel<1><<<ggu, 256, smem_bytes>>>(p_aq, p_wgu, p_sgu, p_as,
                                                  p_guh, nullptr, nullptr, nullptr, HID, 2 * MLPD);
    silu_quant_kernel<<<NTOK, 512>>>(p_guh, p_aq, p_as);
    gemm_bf16_kernel<3><<<g16, 256, smem_bytes>>>(p_aq, p_wd, p_sd, p_as,
                                                  out, nullptr, nullptr, p_x1, MLPD, HID);
    (void)in_sizes; (void)n_in; (void)out_size;
}

// round 14
// speedup vs baseline: 1.0207x; 1.0207x over previous
#include <cuda_runtime.h>
#include <cuda_bf16.h>
#include <cuda_fp16.h>
#include <cstdint>
#include <stdint.h>
#include <math.h>

#define NTOK   4096      // B*S
#define HID    2048
#define NH     16
#define HD     128
#define MLPD   8192
#define SEQL   2048

// ------------------------- persistent device scratch -------------------------
__device__ __nv_bfloat16 g_wqkv[3 * HID * HID];   // concat q|k|v weights
__device__ __nv_bfloat16 g_wo[HID * HID];
__device__ __nv_bfloat16 g_wgu[2 * MLPD * HID];   // concat gate|up weights
__device__ __nv_bfloat16 g_wd[HID * MLPD];
__device__ float g_sqkv[3 * HID], g_so[HID];
__device__ float g_sgu[2 * MLPD], g_sd[HID];

__device__ __nv_bfloat16 g_aq[NTOK * MLPD];   // quantized activations (bf16 ints)
__device__ float g_as[NTOK];                  // per-token activation scales
__device__ __half g_qh[NTOK * HID];           // q fp16, [B,H,S,D] (roped in place)
__device__ __half g_kh[NTOK * HID];           // k fp16, [B,H,S,D]
__device__ __half g_vh[NTOK * HID];           // v fp16, [B,H,S,D]
__device__ __half g_attnoh[NTOK * HID];       // attention output fp16, [T, H*D]
__device__ float g_x1[NTOK * HID];            // residual after attention
__device__ __half g_guh[NTOK * 2 * MLPD];     // [gate|up] fp16, row stride 16384

// ------------------------- fused weight quantization (all 7 matrices, two-pass body) -------------------------
struct QW7 {
    const float* W[7];
    const float* al[7];
    __nv_bfloat16* out[7];
    float* rs[7];
    int K[7];
    int start[7];       // cumulative block start per matrix
};

__global__ void __launch_bounds__(256)
quant_w_all_kernel(QW7 qa) {
    int bid = blockIdx.x;
    int m = 0;
#pragma unroll
    for (int i = 1; i < 7; i++) if (bid >= qa.start[i]) m = i;
    const int o = bid - qa.start[m];
    const int K = qa.K[m];
    const float4* row = (const float4*)(qa.W[m] + (size_t)o * K);
    int nv = K / 4;
    __shared__ float red[256];
    float s = 0.f;
    for (int i = threadIdx.x; i < nv; i += 256) {
        float4 v = row[i];
        s += fabsf(v.x) + fabsf(v.y) + fabsf(v.z) + fabsf(v.w);
    }
    red[threadIdx.x] = s;
    __syncthreads();
    for (int st = 128; st > 0; st >>= 1) {
        if (threadIdx.x < st) red[threadIdx.x] += red[threadIdx.x + st];
        __syncthreads();
    }
    float wsc = red[0] / (float)K + 1e-8f;
    if (threadIdx.x == 0) qa.rs[m][o] = wsc * qa.al[m][o] / 127.0f;
    __nv_bfloat162* orow = (__nv_bfloat162*)(qa.out[m] + (size_t)o * K);
    for (int i = threadIdx.x; i < nv; i += 256) {
        float4 v = row[i];
        float q0 = fminf(fmaxf(rintf(v.x / wsc), -1.f), 1.f);
        float q1 = fminf(fmaxf(rintf(v.y / wsc), -1.f), 1.f);
        float q2 = fminf(fmaxf(rintf(v.z / wsc), -1.f), 1.f);
        float q3 = fminf(fmaxf(rintf(v.w / wsc), -1.f), 1.f);
        orow[i * 2 + 0] = __floats2bfloat162_rn(q0, q1);
        orow[i * 2 + 1] = __floats2bfloat162_rn(q2, q3);
    }
}

// ------------------------- rmsnorm + activation quant (N = 2048, bf16 out) -------------------------
__global__ void rms_quant_kernel(const float* __restrict__ x,
                                 const float* __restrict__ w,
                                 __nv_bfloat16* __restrict__ aq,
                                 float* __restrict__ as_) {
    int t = blockIdx.x;
    const float* row = x + (size_t)t * HID;
    float v[8], h[8];
    float ss = 0.f;
#pragma unroll
    for (int j = 0; j < 8; j++) {
        v[j] = row[j * 256 + threadIdx.x];
        ss += v[j] * v[j];
    }
    __shared__ float red[256];
    red[threadIdx.x] = ss;
    __syncthreads();
    for (int st = 128; st > 0; st >>= 1) {
        if (threadIdx.x < st) red[threadIdx.x] += red[threadIdx.x + st];
        __syncthreads();
    }
    float rms = sqrtf(red[0] / (float)HID + 1e-6f);
    __syncthreads();
    float mx = 0.f;
#pragma unroll
    for (int j = 0; j < 8; j++) {
        h[j] = v[j] / rms * w[j * 256 + threadIdx.x];
        mx = fmaxf(mx, fabsf(h[j]));
    }
    red[threadIdx.x] = mx;
    __syncthreads();
    for (int st = 128; st > 0; st >>= 1) {
        if (threadIdx.x < st) red[threadIdx.x] = fmaxf(red[threadIdx.x], red[threadIdx.x + st]);
        __syncthreads();
    }
    float asc = red[0] + 1e-8f;
    if (threadIdx.x == 0) as_[t] = asc;
    __nv_bfloat16* orow = aq + (size_t)t * HID;
#pragma unroll
    for (int j = 0; j < 8; j++) {
        float q = h[j] / asc * 127.0f;
        q = fminf(fmaxf(q, -128.f), 127.f);
        orow[j * 256 + threadIdx.x] = __float2bfloat16(rintf(q));
    }
}

// ------------------------- activation quant from fp16 (N = 2048, bf16 out) -------------------------
__global__ void act_quant_h_kernel(const __half* __restrict__ x,
                                   __nv_bfloat16* __restrict__ aq,
                                   float* __restrict__ as_) {
    int t = blockIdx.x;
    const __half2* row = (const __half2*)(x + (size_t)t * HID);
    float v[8];
    float mx = 0.f;
#pragma unroll
    for (int j = 0; j < 4; j++) {
        int idx = j * 256 + threadIdx.x;
        float2 f = __half22float2(row[idx]);
        v[j * 2] = f.x; v[j * 2 + 1] = f.y;
        mx = fmaxf(mx, fmaxf(fabsf(f.x), fabsf(f.y)));
    }
    __shared__ float red[256];
    red[threadIdx.x] = mx;
    __syncthreads();
    for (int st = 128; st > 0; st >>= 1) {
        if (threadIdx.x < st) red[threadIdx.x] = fmaxf(red[threadIdx.x], red[threadIdx.x + st]);
        __syncthreads();
    }
    float asc = red[0] + 1e-8f;
    if (threadIdx.x == 0) as_[t] = asc;
    __nv_bfloat162* orow = (__nv_bfloat162*)(aq + (size_t)t * HID);
#pragma unroll
    for (int j = 0; j < 4; j++) {
        int idx = j * 256 + threadIdx.x;
        float q0 = rintf(fminf(fmaxf(v[j * 2] / asc * 127.0f, -128.f), 127.f));
        float q1 = rintf(fminf(fmaxf(v[j * 2 + 1] / asc * 127.0f, -128.f), 127.f));
        orow[idx] = __floats2bfloat162_rn(q0, q1);
    }
}

// ------------------------- fused silu*up + quant (row = [gate(8192)|up(8192)] fp16) -------------------------
__global__ void __launch_bounds__(512)
silu_quant_kernel(const __half* __restrict__ gu,
                  __nv_bfloat16* __restrict__ aq, float* __restrict__ as_) {
    int t = blockIdx.x;
    const __half2* rg = (const __half2*)(gu + (size_t)t * 2 * MLPD);
    const __half2* ru = (const __half2*)(gu + (size_t)t * 2 * MLPD + MLPD);
    float v[16];
    float mx = 0.f;
#pragma unroll
    for (int j = 0; j < 8; j++) {
        int idx = j * 512 + threadIdx.x;
        float2 gx = __half22float2(rg[idx]);
        float2 ux = __half22float2(ru[idx]);
        float y0 = gx.x / (1.0f + __expf(-gx.x)) * ux.x;
        float y1 = gx.y / (1.0f + __expf(-gx.y)) * ux.y;
        v[j * 2] = y0; v[j * 2 + 1] = y1;
        mx = fmaxf(mx, fmaxf(fabsf(y0), fabsf(y1)));
    }
    __shared__ float red[512];
    red[threadIdx.x] = mx;
    __syncthreads();
    for (int st = 256; st > 0; st >>= 1) {
        if (threadIdx.x < st) red[threadIdx.x] = fmaxf(red[threadIdx.x], red[threadIdx.x + st]);
        __syncthreads();
    }
    float asc = red[0] + 1e-8f;
    if (threadIdx.x == 0) as_[t] = asc;
    __nv_bfloat162* orow = (__nv_bfloat162*)(aq + (size_t)t * MLPD);
#pragma unroll
    for (int j = 0; j < 8; j++) {
        int idx = j * 512 + threadIdx.x;
        float q0 = rintf(fminf(fmaxf(v[j * 2] / asc * 127.0f, -128.f), 127.f));
        float q1 = rintf(fminf(fmaxf(v[j * 2 + 1] / asc * 127.0f, -128.f), 127.f));
        orow[idx] = __floats2bfloat162_rn(q0, q1);
    }
}

// ------------------------- mma helpers -------------------------
__device__ __forceinline__ unsigned smem_addr(const void* p) {
    return (unsigned)__cvta_generic_to_shared(p);
}
__device__ __forceinline__ void cp_async16(void* dst, const void* src) {
    asm volatile("cp.async.cg.shared.global [%0], [%1], 16;\n"
                 :: "r"(smem_addr(dst)), "l"(src));
}
__device__ __forceinline__ void cp_commit() { asm volatile("cp.async.commit_group;\n"); }
__device__ __forceinline__ void ldm4(unsigned* r, unsigned addr) {
    asm volatile("ldmatrix.sync.aligned.m8n8.x4.shared.b16 {%0,%1,%2,%3}, [%4];\n"
                 : "=r"(r[0]), "=r"(r[1]), "=r"(r[2]), "=r"(r[3]) : "r"(addr));
}
__device__ __forceinline__ void ldm4t(unsigned* r, unsigned addr) {
    asm volatile("ldmatrix.sync.aligned.m8n8.x4.trans.shared.b16 {%0,%1,%2,%3}, [%4];\n"
                 : "=r"(r[0]), "=r"(r[1]), "=r"(r[2]), "=r"(r[3]) : "r"(addr));
}
__device__ __forceinline__ void mma16816(float* c, const unsigned* a, unsigned b0, unsigned b1) {
    asm volatile(
        "mma.sync.aligned.m16n8k16.row.col.f32.bf16.bf16.f32 "
        "{%0,%1,%2,%3},{%4,%5,%6,%7},{%8,%9},{%0,%1,%2,%3};\n"
        : "+f"(c[0]), "+f"(c[1]), "+f"(c[2]), "+f"(c[3])
        : "r"(a[0]), "r"(a[1]), "r"(a[2]), "r"(a[3]), "r"(b0), "r"(b1));
}
__device__ __forceinline__ void mma16816h(float* c, const unsigned* a, unsigned b0, unsigned b1) {
    asm volatile(
        "mma.sync.aligned.m16n8k16.row.col.f32.f16.f16.f32 "
        "{%0,%1,%2,%3},{%4,%5,%6,%7},{%8,%9},{%0,%1,%2,%3};\n"
        : "+f"(c[0]), "+f"(c[1]), "+f"(c[2]), "+f"(c[3])
        : "r"(a[0]), "r"(a[1]), "r"(a[2]), "r"(a[3]), "r"(b0), "r"(b1));
}
__device__ __forceinline__ unsigned packh2(float a, float b) {
    __half2 h = __floats2half2_rn(a, b);
    return *reinterpret_cast<unsigned*>(&h);
}

// ------------------------- bf16 tensor-core GEMM (validated mainloop) -------------------------
// MODE 1: fp16 C0[t*N+o]
// MODE 2: QKV — fp16 at [B,H,S,D]; buffer chosen from col block (C0=q, C1=k, C2=v)
// MODE 3: fp32 C0[t*N+o] = val + res[t*N+o]
#define BM 128
#define BN 128
#define BK 64
__device__ __forceinline__ int sw_off(int row, int u) {
    return (row * 8 + (u ^ (row & 7))) * 8;
}
__device__ __forceinline__ size_t vaddr(int t, int o) {
    return ((size_t)((t >> 11) * NH + (o >> 7)) * SEQL + (t & (SEQL - 1))) * HD + (o & (HD - 1));
}

template <int MODE>
__global__ void __launch_bounds__(256)
gemm_bf16_kernel(const __nv_bfloat16* __restrict__ A, const __nv_bfloat16* __restrict__ B,
                 const float* __restrict__ rs, const float* __restrict__ asc,
                 void* __restrict__ C0, void* __restrict__ C1, void* __restrict__ C2,
                 const float* __restrict__ res, int K, int N) {
    extern __shared__ __nv_bfloat16 sm[];
    __nv_bfloat16* As = sm;
    __nv_bfloat16* Bs = sm + 2 * BM * BK;

    const int tid = threadIdx.x;
    const int lane = tid & 31;
    const int wid = tid >> 5;
    const int warp_m = wid >> 1;
    const int warp_n = wid & 1;
    const int rowBase = blockIdx.y * BM;
    const int colBase = blockIdx.x * BN;

    float acc[2][8][4];
#pragma unroll
    for (int mt = 0; mt < 2; mt++)
#pragma unroll
        for (int nt = 0; nt < 8; nt++)
#pragma unroll
            for (int i = 0; i < 4; i++) acc[mt][nt][i] = 0.f;

    const int nsteps = K / BK;
    {
#pragma unroll
        for (int it = 0; it < 4; it++) {
            int j = tid + it * 256;
            int row = j >> 3, u = j & 7;
            cp_async16(As + sw_off(row, u), A + (size_t)(rowBase + row) * K + u * 8);
            cp_async16(Bs + sw_off(row, u), B + (size_t)(colBase + row) * K + u * 8);
        }
        cp_commit();
    }

    for (int s = 0; s < nsteps; s++) {
        if (s + 1 < nsteps) {
            __nv_bfloat16* Ab = As + ((s + 1) & 1) * BM * BK;
            __nv_bfloat16* Bb = Bs + ((s + 1) & 1) * BN * BK;
            int k0 = (s + 1) * BK;
#pragma unroll
            for (int it = 0; it < 4; it++) {
                int j = tid + it * 256;
                int row = j >> 3, u = j & 7;
                cp_async16(Ab + sw_off(row, u), A + (size_t)(rowBase + row) * K + k0 + u * 8);
                cp_async16(Bb + sw_off(row, u), B + (size_t)(colBase + row) * K + k0 + u * 8);
            }
            cp_commit();
            asm volatile("cp.async.wait_group 1;\n");
        } else {
            asm volatile("cp.async.wait_group 0;\n");
        }
        __syncthreads();

        const __nv_bfloat16* Ab = As + (s & 1) * BM * BK;
        const __nv_bfloat16* Bb = Bs + (s & 1) * BN * BK;
        const unsigned a_base = smem_addr(Ab);
        const unsigned b_base = smem_addr(Bb);

#pragma unroll
        for (int kc = 0; kc < 4; kc++) {
            const int u = kc * 2 + (lane >> 4);
            unsigned afrag[2][4];
#pragma unroll
            for (int mt = 0; mt < 2; mt++) {
                int row = warp_m * 32 + mt * 16 + (lane & 15);
                ldm4(afrag[mt], a_base + (unsigned)sw_off(row, u) * 2);
            }
            unsigned bfrag[8][2];
#pragma unroll
            for (int np = 0; np < 4; np++) {
                int row = warp_n * 64 + np * 16 + (lane & 15);
                unsigned r[4];
                ldm4(r, b_base + (unsigned)sw_off(row, u) * 2);
                bfrag[np * 2 + 0][0] = r[0]; bfrag[np * 2 + 0][1] = r[2];
                bfrag[np * 2 + 1][0] = r[1]; bfrag[np * 2 + 1][1] = r[3];
            }
#pragma unroll
            for (int mt = 0; mt < 2; mt++)
#pragma unroll
                for (int nt = 0; nt < 8; nt++)
                    mma16816(acc[mt][nt], afrag[mt], bfrag[nt][0], bfrag[nt][1]);
        }
        __syncthreads();
    }

    __half* Csel = nullptr;
    int cshift = 0;
    if (MODE == 2) {
        int which = colBase >> 11;
        Csel = (which == 0) ? (__half*)C0 : (which == 1) ? (__half*)C1 : (__half*)C2;
        cshift = which << 11;
    }

#pragma unroll
    for (int mt = 0; mt < 2; mt++) {
        int r0 = rowBase + warp_m * 32 + mt * 16 + (lane >> 2);
        float sA = asc[r0], sB = asc[r0 + 8];
#pragma unroll
        for (int nt = 0; nt < 8; nt++) {
            int c0 = colBase + warp_n * 64 + nt * 8 + (lane & 3) * 2;
            float rs0 = rs[c0], rs1 = rs[c0 + 1];
            float v00 = acc[mt][nt][0] * rs0 * sA;
            float v01 = acc[mt][nt][1] * rs1 * sA;
            float v10 = acc[mt][nt][2] * rs0 * sB;
            float v11 = acc[mt][nt][3] * rs1 * sB;
            if (MODE == 1) {
                __half2* C = (__half2*)C0;
                C[((size_t)r0 * N + c0) >> 1]       = __floats2half2_rn(v00, v01);
                C[((size_t)(r0 + 8) * N + c0) >> 1] = __floats2half2_rn(v10, v11);
            } else if (MODE == 2) {
                int oc = c0 - cshift;
                *(__half2*)(Csel + vaddr(r0, oc))     = __floats2half2_rn(v00, v01);
                *(__half2*)(Csel + vaddr(r0 + 8, oc)) = __floats2half2_rn(v10, v11);
            } else {
                float* C = (float*)C0;
                C[(size_t)r0 * N + c0]           = v00 + res[(size_t)r0 * N + c0];
                C[(size_t)r0 * N + c0 + 1]       = v01 + res[(size_t)r0 * N + c0 + 1];
                C[(size_t)(r0 + 8) * N + c0]     = v10 + res[(size_t)(r0 + 8) * N + c0];
                C[(size_t)(r0 + 8) * N + c0 + 1] = v11 + res[(size_t)(r0 + 8) * N + c0 + 1];
            }
        }
    }
}

// ------------------------- in-place RoPE on fp16 q,k in [B,H,S,D] -------------------------
__global__ void rope_inplace_kernel(__half* __restrict__ q, __half* __restrict__ k) {
    int idx = blockIdx.x * blockDim.x + threadIdx.x;
    if (idx >= NTOK * NH * 64) return;
    int d = idx & 63;
    int row = idx >> 6;
    int s = row & (SEQL - 1);
    float invf = 1.0f / powf(10000.0f, (float)d / 64.0f);
    float ang = (float)s * invf;
    float sn, c;
    sincosf(ang, &sn, &c);
    size_t base = (size_t)row * HD;
    float x1 = __half2float(q[base + d]), x2 = __half2float(q[base + d + 64]);
    q[base + d]      = __float2half(x1 * c - x2 * sn);
    q[base + d + 64] = __float2half(x2 * c + x1 * sn);
    float y1 = __half2float(k[base + d]), y2 = __half2float(k[base + d + 64]);
    k[base + d]      = __float2half(y1 * c - y2 * sn);
    k[base + d + 64] = __float2half(y2 * c + y1 * sn);
}

// ------------------------- fp16 mma flash attention (validated) -------------------------
__device__ __forceinline__ int sw16(int row, int u) {
    return row * 128 + (((u ^ row) & 7) | (u & 8)) * 8;
}

__device__ __forceinline__ void attn_load_tile(__half* Ks, __half* Vs,
                                               const __half* kb_, const __half* vb_,
                                               int tid) {
#pragma unroll
    for (int it = 0; it < 8; it++) {
        int idx = tid + it * 128;
        int row = idx >> 4, u = idx & 15;
        cp_async16(Ks + sw16(row, u), kb_ + (size_t)row * HD + u * 8);
        cp_async16(Vs + sw16(row, u), vb_ + (size_t)row * HD + u * 8);
    }
}

__global__ void __launch_bounds__(128)
attn_mma_kernel(const __half* __restrict__ qh, const __half* __restrict__ kh,
                const __half* __restrict__ vh, const int* __restrict__ mask,
                __half* __restrict__ out) {
    extern __shared__ __half ash[];
    __half* Qs = ash;
    __half* KsA[2] = {ash + 8192, ash + 16384};
    __half* VsA[2] = {ash + 24576, ash + 32768};

    const int tid = threadIdx.x;
    const int lane = tid & 31;
    const int wid = tid >> 5;
    const int bx = blockIdx.x;
    const int bh = bx & 31;
    const int qslot = bx >> 5;
    const int qb = (31 - qslot) * 64;
    const int b = bh >> 4;
    const int h = bh & 15;

    const __half* qbase = qh + ((size_t)bh * SEQL + qb) * HD;
    const __half* kbase = kh + (size_t)bh * SEQL * HD;
    const __half* vbase = vh + (size_t)bh * SEQL * HD;
    const int* mrow = mask + b * SEQL;
    const int ntiles = qb / 64 + 1;

#pragma unroll
    for (int it = 0; it < 8; it++) {
        int idx = tid + it * 128;
        int row = idx >> 4, u = idx & 15;
        cp_async16(Qs + sw16(row, u), qbase + (size_t)row * HD + u * 8);
    }
    attn_load_tile(KsA[0], VsA[0], kbase, vbase, tid);
    cp_commit();
    if (ntiles > 1) attn_load_tile(KsA[1], VsA[1], kbase + 64 * HD, vbase + 64 * HD, tid);
    cp_commit();

    float oacc[16][4];
#pragma unroll
    for (int i = 0; i < 16; i++) { oacc[i][0] = oacc[i][1] = oacc[i][2] = oacc[i][3] = 0.f; }
    float m0 = -1e30f, m1 = -1e30f, l0 = 0.f, l1 = 0.f;
    const float scale = 0.08838834764831845f;
    const int r = lane >> 2;
    const int c2 = (lane & 3) * 2;
    const int qr0 = qb + wid * 16 + r;
    const unsigned qs_base = smem_addr(Qs);

    for (int t = 0; t < ntiles; t++) {
        asm volatile("cp.async.wait_group 1;\n");
        __syncthreads();
        const int kb = t * 64;
        const unsigned k_base = smem_addr(KsA[t & 1]);
        const unsigned v_base = smem_addr(VsA[t & 1]);

        float sacc[8][4];
#pragma unroll
        for (int nt = 0; nt < 8; nt++) { sacc[nt][0] = sacc[nt][1] = sacc[nt][2] = sacc[nt][3] = 0.f; }
#pragma unroll
        for (int kc = 0; kc < 8; kc++) {
            const int u = kc * 2 + (lane >> 4);
            unsigned afrag[4];
            ldm4(afrag, qs_base + (unsigned)sw16(wid * 16 + (lane & 15), u) * 2);
#pragma unroll
            for (int np = 0; np < 4; np++) {
                unsigned rr[4];
                ldm4(rr, k_base + (unsigned)sw16(np * 16 + (lane & 15), u) * 2);
                mma16816h(sacc[np * 2 + 0], afrag, rr[0], rr[2]);
                mma16816h(sacc[np * 2 + 1], afrag, rr[1], rr[3]);
            }
        }

        float mx0 = -1e30f, mx1 = -1e30f;
#pragma unroll
        for (int nt = 0; nt < 8; nt++) {
#pragma unroll
            for (int i = 0; i < 4; i++) {
                int col = kb + nt * 8 + c2 + (i & 1);
                int qr = qr0 + ((i >> 1) << 3);
                float s = sacc[nt][i] * scale;
                bool dead = (col > qr) || (mrow[col] == 0);
                s = dead ? -10000.f : fmaxf(s, -10000.f);
                sacc[nt][i] = s;
                if (i < 2) mx0 = fmaxf(mx0, s); else mx1 = fmaxf(mx1, s);
            }
        }
        mx0 = fmaxf(mx0, __shfl_xor_sync(0xffffffffu, mx0, 1));
        mx0 = fmaxf(mx0, __shfl_xor_sync(0xffffffffu, mx0, 2));
        mx1 = fmaxf(mx1, __shfl_xor_sync(0xffffffffu, mx1, 1));
        mx1 = fmaxf(mx1, __shfl_xor_sync(0xffffffffu, mx1, 2));
        float nm0 = fmaxf(m0, mx0), nm1 = fmaxf(m1, mx1);
        float cor0 = __expf(m0 - nm0), cor1 = __expf(m1 - nm1);
        float ls0 = 0.f, ls1 = 0.f;
#pragma unroll
        for (int nt = 0; nt < 8; nt++) {
#pragma unroll
            for (int i = 0; i < 4; i++) {
                float p = __expf(sacc[nt][i] - ((i < 2) ? nm0 : nm1));
                sacc[nt][i] = p;
                if (i < 2) ls0 += p; else ls1 += p;
            }
        }
        ls0 += __shfl_xor_sync(0xffffffffu, ls0, 1);
        ls0 += __shfl_xor_sync(0xffffffffu, ls0, 2);
        ls1 += __shfl_xor_sync(0xffffffffu, ls1, 1);
        ls1 += __shfl_xor_sync(0xffffffffu, ls1, 2);
        l0 = l0 * cor0 + ls0;
        l1 = l1 * cor1 + ls1;
        m0 = nm0; m1 = nm1;
#pragma unroll
        for (int i = 0; i < 16; i++) {
            oacc[i][0] *= cor0; oacc[i][1] *= cor0;
            oacc[i][2] *= cor1; oacc[i][3] *= cor1;
        }

#pragma unroll
        for (int kc2 = 0; kc2 < 4; kc2++) {
            unsigned pa[4];
            pa[0] = packh2(sacc[2 * kc2][0], sacc[2 * kc2][1]);
            pa[1] = packh2(sacc[2 * kc2][2], sacc[2 * kc2][3]);
            pa[2] = packh2(sacc[2 * kc2 + 1][0], sacc[2 * kc2 + 1][1]);
            pa[3] = packh2(sacc[2 * kc2 + 1][2], sacc[2 * kc2 + 1][3]);
#pragma unroll
            for (int dnp = 0; dnp < 8; dnp++) {
                unsigned rr[4];
                ldm4t(rr, v_base + (unsigned)sw16(kc2 * 16 + (lane & 15), dnp * 2 + (lane >> 4)) * 2);
                mma16816h(oacc[dnp * 2 + 0], pa, rr[0], rr[1]);
                mma16816h(oacc[dnp * 2 + 1], pa, rr[2], rr[3]);
            }
        }
        __syncthreads();
        if (t + 2 < ntiles)
            attn_load_tile(KsA[t & 1], VsA[t & 1], kbase + (size_t)(t + 2) * 64 * HD,
                           vbase + (size_t)(t + 2) * 64 * HD, tid);
        cp_commit();
    }

    float inv0 = 1.f / l0, inv1 = 1.f / l1;
    size_t o0 = ((size_t)b * SEQL + qr0) * HID + h * HD;
    size_t o1 = o0 + 8 * HID;
#pragma unroll
    for (int dnt = 0; dnt < 16; dnt++) {
        int d = dnt * 8 + c2;
        *(__half2*)(out + o0 + d) = __floats2half2_rn(oacc[dnt][0] * inv0, oacc[dnt][1] * inv0);
        *(__half2*)(out + o1 + d) = __floats2half2_rn(oacc[dnt][2] * inv1, oacc[dnt][3] * inv1);
    }
}

// ------------------------- host orchestration -------------------------
extern "C" void kernel_launch(void* const* d_in, const int* in_sizes, int n_in,
                              void* d_out, int out_size) {
    const float* x     = (const float*)d_in[0];
    const int*   amask = (const int*)d_in[1];
    const float* wq = (const float*)d_in[2];   const float* aq_a = (const float*)d_in[3];
    const float* wk = (const float*)d_in[4];   const float* ak_a = (const float*)d_in[5];
    const float* wv = (const float*)d_in[6];   const float* av_a = (const float*)d_in[7];
    const float* wo = (const float*)d_in[8];   const float* ao_a = (const float*)d_in[9];
    const float* wg = (const float*)d_in[10];  const float* ag_a = (const float*)d_in[11];
    const float* wu = (const float*)d_in[12];  const float* au_a = (const float*)d_in[13];
    const float* wd = (const float*)d_in[14];  const float* ad_a = (const float*)d_in[15];
    const float* n1 = (const float*)d_in[16];
    const float* n2 = (const float*)d_in[17];
    float* out = (float*)d_out;

    __nv_bfloat16 *p_wqkv, *p_wo, *p_wgu, *p_wd, *p_aq;
    __half *p_qh, *p_kh, *p_vh, *p_guh, *p_attnoh;
    float *p_sqkv, *p_so, *p_sgu, *p_sd;
    float *p_as, *p_x1;
    cudaGetSymbolAddress((void**)&p_wqkv, g_wqkv);
    cudaGetSymbolAddress((void**)&p_wo, g_wo);
    cudaGetSymbolAddress((void**)&p_wgu, g_wgu);
    cudaGetSymbolAddress((void**)&p_wd, g_wd);
    cudaGetSymbolAddress((void**)&p_sqkv, g_sqkv);
    cudaGetSymbolAddress((void**)&p_so, g_so);
    cudaGetSymbolAddress((void**)&p_sgu, g_sgu);
    cudaGetSymbolAddress((void**)&p_sd, g_sd);
    cudaGetSymbolAddress((void**)&p_aq, g_aq);
    cudaGetSymbolAddress((void**)&p_as, g_as);
    cudaGetSymbolAddress((void**)&p_qh, g_qh);
    cudaGetSymbolAddress((void**)&p_kh, g_kh);
    cudaGetSymbolAddress((void**)&p_vh, g_vh);
    cudaGetSymbolAddress((void**)&p_attnoh, g_attnoh);
    cudaGetSymbolAddress((void**)&p_x1, g_x1);
    cudaGetSymbolAddress((void**)&p_guh, g_guh);

    const int smem_bytes = 2 * (BM * BK + BN * BK) * 2;   // 65536
    cudaFuncSetAttribute(gemm_bf16_kernel<1>, cudaFuncAttributeMaxDynamicSharedMemorySize, smem_bytes);
    cudaFuncSetAttribute(gemm_bf16_kernel<2>, cudaFuncAttributeMaxDynamicSharedMemorySize, smem_bytes);
    cudaFuncSetAttribute(gemm_bf16_kernel<3>, cudaFuncAttributeMaxDynamicSharedMemorySize, smem_bytes);
    const int attn_smem = 40960 * 2;                      // 81920
    cudaFuncSetAttribute(attn_mma_kernel, cudaFuncAttributeMaxDynamicSharedMemorySize, attn_smem);

    // 1) fused weight quantization (one launch for all 7 matrices)
    QW7 qa;
    qa.W[0] = wq; qa.al[0] = aq_a; qa.out[0] = p_wqkv;                         qa.rs[0] = p_sqkv;           qa.K[0] = HID;
    qa.W[1] = wk; qa.al[1] = ak_a; qa.out[1] = p_wqkv + (size_t)HID * HID;     qa.rs[1] = p_sqkv + HID;     qa.K[1] = HID;
    qa.W[2] = wv; qa.al[2] = av_a; qa.out[2] = p_wqkv + 2 * (size_t)HID * HID; qa.rs[2] = p_sqkv + 2 * HID; qa.K[2] = HID;
    qa.W[3] = wo; qa.al[3] = ao_a; qa.out[3] = p_wo;                           qa.rs[3] = p_so;             qa.K[3] = HID;
    qa.W[4] = wg; qa.al[4] = ag_a; qa.out[4] = p_wgu;                          qa.rs[4] = p_sgu;            qa.K[4] = HID;
    qa.W[5] = wu; qa.al[5] = au_a; qa.out[5] = p_wgu + (size_t)MLPD * HID;     qa.rs[5] = p_sgu + MLPD;     qa.K[5] = HID;
    qa.W[6] = wd; qa.al[6] = ad_a; qa.out[6] = p_wd;                           qa.rs[6] = p_sd;             qa.K[6] = MLPD;
    qa.start[0] = 0;      qa.start[1] = 2048;  qa.start[2] = 4096;  qa.start[3] = 6144;
    qa.start[4] = 8192;   qa.start[5] = 16384; qa.start[6] = 24576;
    quant_w_all_kernel<<<26624, 256>>>(qa);

    // 2) rmsnorm + quantize input
    rms_quant_kernel<<<NTOK, 256>>>(x, n1, p_aq, p_as);

    // 3) fused QKV projection -> fp16 [B,H,S,D]
    dim3 gqkv(3 * HID / BN, NTOK / BM);
    gemm_bf16_kernel<2><<<gqkv, 256, smem_bytes>>>(p_aq, p_wqkv, p_sqkv, p_as,
                                                   p_qh, p_kh, p_vh, nullptr, HID, HID);

    // 4) in-place rope on q,k
    rope_inplace_kernel<<<(NTOK * NH * 64 + 255) / 256, 256>>>(p_qh, p_kh);

    // 5) mma flash attention (fp16 out)
    attn_mma_kernel<<<(SEQL / 64) * 32, 128, attn_smem>>>(p_qh, p_kh, p_vh, amask, p_attnoh);

    // 6) output projection with fused residual: x1 = x + attno @ wo
    act_quant_h_kernel<<<NTOK, 256>>>(p_attnoh, p_aq, p_as);
    dim3 g16(HID / BN, NTOK / BM);
    gemm_bf16_kernel<3><<<g16, 256, smem_bytes>>>(p_aq, p_wo, p_so, p_as,
                                                  p_x1, nullptr, nullptr, x, HID, HID);

    // 7) rmsnorm + quant of x1
    rms_quant_kernel<<<NTOK, 256>>>(p_x1, n2, p_aq, p_as);

    // 8) MLP: fused gate|up GEMM -> fp16, silu+quant, down GEMM with residual into d_out
    dim3 ggu(2 * MLPD / BN, NTOK / BM);
    gemm_bf16_kernel<1><<<ggu, 256, smem_bytes>>>(p_aq, p_wgu, p_sgu, p_as,
                                                  p_guh, nullptr, nullptr, nullptr, HID, 2 * MLPD);
    silu_quant_kernel<<<NTOK, 512>>>(p_guh, p_aq, p_as);
    gemm_bf16_kernel<3><<<g16, 256, smem_bytes>>>(p_aq, p_wd, p_sd, p_as,
                                                  out, nullptr, nullptr, p_x1, MLPD, HID);
    (void)in_sizes; (void)n_in; (void)out_size;
}

// round 15
// speedup vs baseline: 1.0221x; 1.0013x over previous
#include <cuda_runtime.h>
#include <cuda_bf16.h>
#include <cuda_fp16.h>
#include <cstdint>
#include <stdint.h>
#include <math.h>

#define NTOK   4096      // B*S
#define HID    2048
#define NH     16
#define HD     128
#define MLPD   8192
#define SEQL   2048

// ------------------------- persistent device scratch -------------------------
__device__ __nv_bfloat16 g_wqkv[3 * HID * HID];   // concat q|k|v weights
__device__ __nv_bfloat16 g_wo[HID * HID];
__device__ __nv_bfloat16 g_wgu[2 * MLPD * HID];   // concat gate|up weights
__device__ __nv_bfloat16 g_wd[HID * MLPD];
__device__ float g_sqkv[3 * HID], g_so[HID];
__device__ float g_sgu[2 * MLPD], g_sd[HID];

__device__ __nv_bfloat16 g_aq[NTOK * MLPD];   // quantized activations (bf16 ints)
__device__ float g_as[NTOK];                  // per-token activation scales
__device__ __half g_qh[NTOK * HID];           // q fp16, [B,H,S,D] (roped in place)
__device__ __half g_kh[NTOK * HID];           // k fp16, [B,H,S,D]
__device__ __half g_vh[NTOK * HID];           // v fp16, [B,H,S,D]
__device__ __half g_attnoh[NTOK * HID];       // attention output fp16, [T, H*D]
__device__ float g_x1[NTOK * HID];            // residual after attention
__device__ __half g_guh[NTOK * 2 * MLPD];     // [gate|up] fp16, row stride 16384

// ------------------------- fused weight quantization (all 7 matrices, two-pass body) -------------------------
struct QW7 {
    const float* W[7];
    const float* al[7];
    __nv_bfloat16* out[7];
    float* rs[7];
    int K[7];
    int start[7];       // cumulative block start per matrix
};

__global__ void __launch_bounds__(256)
quant_w_all_kernel(QW7 qa) {
    int bid = blockIdx.x;
    int m = 0;
#pragma unroll
    for (int i = 1; i < 7; i++) if (bid >= qa.start[i]) m = i;
    const int o = bid - qa.start[m];
    const int K = qa.K[m];
    const float4* row = (const float4*)(qa.W[m] + (size_t)o * K);
    int nv = K / 4;
    __shared__ float red[256];
    float s = 0.f;
    for (int i = threadIdx.x; i < nv; i += 256) {
        float4 v = row[i];
        s += fabsf(v.x) + fabsf(v.y) + fabsf(v.z) + fabsf(v.w);
    }
    red[threadIdx.x] = s;
    __syncthreads();
    for (int st = 128; st > 0; st >>= 1) {
        if (threadIdx.x < st) red[threadIdx.x] += red[threadIdx.x + st];
        __syncthreads();
    }
    float wsc = red[0] / (float)K + 1e-8f;
    if (threadIdx.x == 0) qa.rs[m][o] = wsc * qa.al[m][o] / 127.0f;
    __nv_bfloat162* orow = (__nv_bfloat162*)(qa.out[m] + (size_t)o * K);
    for (int i = threadIdx.x; i < nv; i += 256) {
        float4 v = row[i];
        float q0 = fminf(fmaxf(rintf(v.x / wsc), -1.f), 1.f);
        float q1 = fminf(fmaxf(rintf(v.y / wsc), -1.f), 1.f);
        float q2 = fminf(fmaxf(rintf(v.z / wsc), -1.f), 1.f);
        float q3 = fminf(fmaxf(rintf(v.w / wsc), -1.f), 1.f);
        orow[i * 2 + 0] = __floats2bfloat162_rn(q0, q1);
        orow[i * 2 + 1] = __floats2bfloat162_rn(q2, q3);
    }
}

// ------------------------- rmsnorm + activation quant (N = 2048, bf16 out) -------------------------
__global__ void rms_quant_kernel(const float* __restrict__ x,
                                 const float* __restrict__ w,
                                 __nv_bfloat16* __restrict__ aq,
                                 float* __restrict__ as_) {
    int t = blockIdx.x;
    const float* row = x + (size_t)t * HID;
    float v[8], h[8];
    float ss = 0.f;
#pragma unroll
    for (int j = 0; j < 8; j++) {
        v[j] = row[j * 256 + threadIdx.x];
        ss += v[j] * v[j];
    }
    __shared__ float red[256];
    red[threadIdx.x] = ss;
    __syncthreads();
    for (int st = 128; st > 0; st >>= 1) {
        if (threadIdx.x < st) red[threadIdx.x] += red[threadIdx.x + st];
        __syncthreads();
    }
    float rms = sqrtf(red[0] / (float)HID + 1e-6f);
    __syncthreads();
    float mx = 0.f;
#pragma unroll
    for (int j = 0; j < 8; j++) {
        h[j] = v[j] / rms * w[j * 256 + threadIdx.x];
        mx = fmaxf(mx, fabsf(h[j]));
    }
    red[threadIdx.x] = mx;
    __syncthreads();
    for (int st = 128; st > 0; st >>= 1) {
        if (threadIdx.x < st) red[threadIdx.x] = fmaxf(red[threadIdx.x], red[threadIdx.x + st]);
        __syncthreads();
    }
    float asc = red[0] + 1e-8f;
    if (threadIdx.x == 0) as_[t] = asc;
    __nv_bfloat16* orow = aq + (size_t)t * HID;
#pragma unroll
    for (int j = 0; j < 8; j++) {
        float q = h[j] / asc * 127.0f;
        q = fminf(fmaxf(q, -128.f), 127.f);
        orow[j * 256 + threadIdx.x] = __float2bfloat16(rintf(q));
    }
}

// ------------------------- activation quant from fp16 (N = 2048, bf16 out) -------------------------
__global__ void act_quant_h_kernel(const __half* __restrict__ x,
                                   __nv_bfloat16* __restrict__ aq,
                                   float* __restrict__ as_) {
    int t = blockIdx.x;
    const __half2* row = (const __half2*)(x + (size_t)t * HID);
    float v[8];
    float mx = 0.f;
#pragma unroll
    for (int j = 0; j < 4; j++) {
        int idx = j * 256 + threadIdx.x;
        float2 f = __half22float2(row[idx]);
        v[j * 2] = f.x; v[j * 2 + 1] = f.y;
        mx = fmaxf(mx, fmaxf(fabsf(f.x), fabsf(f.y)));
    }
    __shared__ float red[256];
    red[threadIdx.x] = mx;
    __syncthreads();
    for (int st = 128; st > 0; st >>= 1) {
        if (threadIdx.x < st) red[threadIdx.x] = fmaxf(red[threadIdx.x], red[threadIdx.x + st]);
        __syncthreads();
    }
    float asc = red[0] + 1e-8f;
    if (threadIdx.x == 0) as_[t] = asc;
    __nv_bfloat162* orow = (__nv_bfloat162*)(aq + (size_t)t * HID);
#pragma unroll
    for (int j = 0; j < 4; j++) {
        int idx = j * 256 + threadIdx.x;
        float q0 = rintf(fminf(fmaxf(v[j * 2] / asc * 127.0f, -128.f), 127.f));
        float q1 = rintf(fminf(fmaxf(v[j * 2 + 1] / asc * 127.0f, -128.f), 127.f));
        orow[idx] = __floats2bfloat162_rn(q0, q1);
    }
}

// ------------------------- fused silu*up + quant (row = [gate(8192)|up(8192)] fp16) -------------------------
__global__ void __launch_bounds__(512)
silu_quant_kernel(const __half* __restrict__ gu,
                  __nv_bfloat16* __restrict__ aq, float* __restrict__ as_) {
    int t = blockIdx.x;
    const __half2* rg = (const __half2*)(gu + (size_t)t * 2 * MLPD);
    const __half2* ru = (const __half2*)(gu + (size_t)t * 2 * MLPD + MLPD);
    float v[16];
    float mx = 0.f;
#pragma unroll
    for (int j = 0; j < 8; j++) {
        int idx = j * 512 + threadIdx.x;
        float2 gx = __half22float2(rg[idx]);
        float2 ux = __half22float2(ru[idx]);
        float y0 = gx.x / (1.0f + __expf(-gx.x)) * ux.x;
        float y1 = gx.y / (1.0f + __expf(-gx.y)) * ux.y;
        v[j * 2] = y0; v[j * 2 + 1] = y1;
        mx = fmaxf(mx, fmaxf(fabsf(y0), fabsf(y1)));
    }
    __shared__ float red[512];
    red[threadIdx.x] = mx;
    __syncthreads();
    for (int st = 256; st > 0; st >>= 1) {
        if (threadIdx.x < st) red[threadIdx.x] = fmaxf(red[threadIdx.x], red[threadIdx.x + st]);
        __syncthreads();
    }
    float asc = red[0] + 1e-8f;
    if (threadIdx.x == 0) as_[t] = asc;
    __nv_bfloat162* orow = (__nv_bfloat162*)(aq + (size_t)t * MLPD);
#pragma unroll
    for (int j = 0; j < 8; j++) {
        int idx = j * 512 + threadIdx.x;
        float q0 = rintf(fminf(fmaxf(v[j * 2] / asc * 127.0f, -128.f), 127.f));
        float q1 = rintf(fminf(fmaxf(v[j * 2 + 1] / asc * 127.0f, -128.f), 127.f));
        orow[idx] = __floats2bfloat162_rn(q0, q1);
    }
}

// ------------------------- mma helpers -------------------------
__device__ __forceinline__ unsigned smem_addr(const void* p) {
    return (unsigned)__cvta_generic_to_shared(p);
}
__device__ __forceinline__ void cp_async16(void* dst, const void* src) {
    asm volatile("cp.async.cg.shared.global [%0], [%1], 16;\n"
                 :: "r"(smem_addr(dst)), "l"(src));
}
__device__ __forceinline__ void cp_commit() { asm volatile("cp.async.commit_group;\n"); }
__device__ __forceinline__ void ldm4(unsigned* r, unsigned addr) {
    asm volatile("ldmatrix.sync.aligned.m8n8.x4.shared.b16 {%0,%1,%2,%3}, [%4];\n"
                 : "=r"(r[0]), "=r"(r[1]), "=r"(r[2]), "=r"(r[3]) : "r"(addr));
}
__device__ __forceinline__ void ldm4t(unsigned* r, unsigned addr) {
    asm volatile("ldmatrix.sync.aligned.m8n8.x4.trans.shared.b16 {%0,%1,%2,%3}, [%4];\n"
                 : "=r"(r[0]), "=r"(r[1]), "=r"(r[2]), "=r"(r[3]) : "r"(addr));
}
__device__ __forceinline__ void mma16816(float* c, const unsigned* a, unsigned b0, unsigned b1) {
    asm volatile(
        "mma.sync.aligned.m16n8k16.row.col.f32.bf16.bf16.f32 "
        "{%0,%1,%2,%3},{%4,%5,%6,%7},{%8,%9},{%0,%1,%2,%3};\n"
        : "+f"(c[0]), "+f"(c[1]), "+f"(c[2]), "+f"(c[3])
        : "r"(a[0]), "r"(a[1]), "r"(a[2]), "r"(a[3]), "r"(b0), "r"(b1));
}
__device__ __forceinline__ void mma16816h(float* c, const unsigned* a, unsigned b0, unsigned b1) {
    asm volatile(
        "mma.sync.aligned.m16n8k16.row.col.f32.f16.f16.f32 "
        "{%0,%1,%2,%3},{%4,%5,%6,%7},{%8,%9},{%0,%1,%2,%3};\n"
        : "+f"(c[0]), "+f"(c[1]), "+f"(c[2]), "+f"(c[3])
        : "r"(a[0]), "r"(a[1]), "r"(a[2]), "r"(a[3]), "r"(b0), "r"(b1));
}
__device__ __forceinline__ unsigned packh2(float a, float b) {
    __half2 h = __floats2half2_rn(a, b);
    return *reinterpret_cast<unsigned*>(&h);
}

// ------------------------- bf16 tensor-core GEMM (validated mainloop) -------------------------
// MODE 1: fp16 C0[t*N+o]
// MODE 2: QKV — fp16 at [B,H,S,D]; buffer chosen from col block (C0=q, C1=k, C2=v)
// MODE 3: fp32 C0[t*N+o] = val + res[t*N+o]
#define BM 128
#define BN 128
#define BK 64
__device__ __forceinline__ int sw_off(int row, int u) {
    return (row * 8 + (u ^ (row & 7))) * 8;
}
__device__ __forceinline__ size_t vaddr(int t, int o) {
    return ((size_t)((t >> 11) * NH + (o >> 7)) * SEQL + (t & (SEQL - 1))) * HD + (o & (HD - 1));
}

template <int MODE>
__global__ void __launch_bounds__(256)
gemm_bf16_kernel(const __nv_bfloat16* __restrict__ A, const __nv_bfloat16* __restrict__ B,
                 const float* __restrict__ rs, const float* __restrict__ asc,
                 void* __restrict__ C0, void* __restrict__ C1, void* __restrict__ C2,
                 const float* __restrict__ res, int K, int N) {
    extern __shared__ __nv_bfloat16 sm[];
    __nv_bfloat16* As = sm;
    __nv_bfloat16* Bs = sm + 2 * BM * BK;

    const int tid = threadIdx.x;
    const int lane = tid & 31;
    const int wid = tid >> 5;
    const int warp_m = wid >> 1;
    const int warp_n = wid & 1;
    const int rowBase = blockIdx.y * BM;
    const int colBase = blockIdx.x * BN;

    float acc[2][8][4];
#pragma unroll
    for (int mt = 0; mt < 2; mt++)
#pragma unroll
        for (int nt = 0; nt < 8; nt++)
#pragma unroll
            for (int i = 0; i < 4; i++) acc[mt][nt][i] = 0.f;

    const int nsteps = K / BK;
    {
#pragma unroll
        for (int it = 0; it < 4; it++) {
            int j = tid + it * 256;
            int row = j >> 3, u = j & 7;
            cp_async16(As + sw_off(row, u), A + (size_t)(rowBase + row) * K + u * 8);
            cp_async16(Bs + sw_off(row, u), B + (size_t)(colBase + row) * K + u * 8);
        }
        cp_commit();
    }

    for (int s = 0; s < nsteps; s++) {
        if (s + 1 < nsteps) {
            __nv_bfloat16* Ab = As + ((s + 1) & 1) * BM * BK;
            __nv_bfloat16* Bb = Bs + ((s + 1) & 1) * BN * BK;
            int k0 = (s + 1) * BK;
#pragma unroll
            for (int it = 0; it < 4; it++) {
                int j = tid + it * 256;
                int row = j >> 3, u = j & 7;
                cp_async16(Ab + sw_off(row, u), A + (size_t)(rowBase + row) * K + k0 + u * 8);
                cp_async16(Bb + sw_off(row, u), B + (size_t)(colBase + row) * K + k0 + u * 8);
            }
            cp_commit();
            asm volatile("cp.async.wait_group 1;\n");
        } else {
            asm volatile("cp.async.wait_group 0;\n");
        }
        __syncthreads();

        const __nv_bfloat16* Ab = As + (s & 1) * BM * BK;
        const __nv_bfloat16* Bb = Bs + (s & 1) * BN * BK;
        const unsigned a_base = smem_addr(Ab);
        const unsigned b_base = smem_addr(Bb);

#pragma unroll
        for (int kc = 0; kc < 4; kc++) {
            const int u = kc * 2 + (lane >> 4);
            unsigned afrag[2][4];
#pragma unroll
            for (int mt = 0; mt < 2; mt++) {
                int row = warp_m * 32 + mt * 16 + (lane & 15);
                ldm4(afrag[mt], a_base + (unsigned)sw_off(row, u) * 2);
            }
            unsigned bfrag[8][2];
#pragma unroll
            for (int np = 0; np < 4; np++) {
                int row = warp_n * 64 + np * 16 + (lane & 15);
                unsigned r[4];
                ldm4(r, b_base + (unsigned)sw_off(row, u) * 2);
                bfrag[np * 2 + 0][0] = r[0]; bfrag[np * 2 + 0][1] = r[2];
                bfrag[np * 2 + 1][0] = r[1]; bfrag[np * 2 + 1][1] = r[3];
            }
#pragma unroll
            for (int mt = 0; mt < 2; mt++)
#pragma unroll
                for (int nt = 0; nt < 8; nt++)
                    mma16816(acc[mt][nt], afrag[mt], bfrag[nt][0], bfrag[nt][1]);
        }
        __syncthreads();
    }

    __half* Csel = nullptr;
    int cshift = 0;
    if (MODE == 2) {
        int which = colBase >> 11;
        Csel = (which == 0) ? (__half*)C0 : (which == 1) ? (__half*)C1 : (__half*)C2;
        cshift = which << 11;
    }

#pragma unroll
    for (int mt = 0; mt < 2; mt++) {
        int r0 = rowBase + warp_m * 32 + mt * 16 + (lane >> 2);
        float sA = asc[r0], sB = asc[r0 + 8];
#pragma unroll
        for (int nt = 0; nt < 8; nt++) {
            int c0 = colBase + warp_n * 64 + nt * 8 + (lane & 3) * 2;
            float rs0 = rs[c0], rs1 = rs[c0 + 1];
            float v00 = acc[mt][nt][0] * rs0 * sA;
            float v01 = acc[mt][nt][1] * rs1 * sA;
            float v10 = acc[mt][nt][2] * rs0 * sB;
            float v11 = acc[mt][nt][3] * rs1 * sB;
            if (MODE == 1) {
                __half2* C = (__half2*)C0;
                C[((size_t)r0 * N + c0) >> 1]       = __floats2half2_rn(v00, v01);
                C[((size_t)(r0 + 8) * N + c0) >> 1] = __floats2half2_rn(v10, v11);
            } else if (MODE == 2) {
                int oc = c0 - cshift;
                *(__half2*)(Csel + vaddr(r0, oc))     = __floats2half2_rn(v00, v01);
                *(__half2*)(Csel + vaddr(r0 + 8, oc)) = __floats2half2_rn(v10, v11);
            } else {
                float* C = (float*)C0;
                C[(size_t)r0 * N + c0]           = v00 + res[(size_t)r0 * N + c0];
                C[(size_t)r0 * N + c0 + 1]       = v01 + res[(size_t)r0 * N + c0 + 1];
                C[(size_t)(r0 + 8) * N + c0]     = v10 + res[(size_t)(r0 + 8) * N + c0];
                C[(size_t)(r0 + 8) * N + c0 + 1] = v11 + res[(size_t)(r0 + 8) * N + c0 + 1];
            }
        }
    }
}

// ------------------------- in-place RoPE on fp16 q,k in [B,H,S,D] -------------------------
// invf = 1/10000^(d/64) computed as exp2f(-log2(10000)/64 * d): one MUFU op vs powf's slow path.
__global__ void rope_inplace_kernel(__half* __restrict__ q, __half* __restrict__ k) {
    int idx = blockIdx.x * blockDim.x + threadIdx.x;
    if (idx >= NTOK * NH * 64) return;
    int d = idx & 63;
    int row = idx >> 6;
    int s = row & (SEQL - 1);
    float invf = exp2f(-0.20762050593046014f * (float)d);
    float ang = (float)s * invf;
    float sn, c;
    sincosf(ang, &sn, &c);
    size_t base = (size_t)row * HD;
    float x1 = __half2float(q[base + d]), x2 = __half2float(q[base + d + 64]);
    q[base + d]      = __float2half(x1 * c - x2 * sn);
    q[base + d + 64] = __float2half(x2 * c + x1 * sn);
    float y1 = __half2float(k[base + d]), y2 = __half2float(k[base + d + 64]);
    k[base + d]      = __float2half(y1 * c - y2 * sn);
    k[base + d + 64] = __float2half(y2 * c + y1 * sn);
}

// ------------------------- fp16 mma flash attention (validated) -------------------------
__device__ __forceinline__ int sw16(int row, int u) {
    return row * 128 + (((u ^ row) & 7) | (u & 8)) * 8;
}

__device__ __forceinline__ void attn_load_tile(__half* Ks, __half* Vs,
                                               const __half* kb_, const __half* vb_,
                                               int tid) {
#pragma unroll
    for (int it = 0; it < 8; it++) {
        int idx = tid + it * 128;
        int row = idx >> 4, u = idx & 15;
        cp_async16(Ks + sw16(row, u), kb_ + (size_t)row * HD + u * 8);
        cp_async16(Vs + sw16(row, u), vb_ + (size_t)row * HD + u * 8);
    }
}

__global__ void __launch_bounds__(128)
attn_mma_kernel(const __half* __restrict__ qh, const __half* __restrict__ kh,
                const __half* __restrict__ vh, const int* __restrict__ mask,
                __half* __restrict__ out) {
    extern __shared__ __half ash[];
    __half* Qs = ash;
    __half* KsA[2] = {ash + 8192, ash + 16384};
    __half* VsA[2] = {ash + 24576, ash + 32768};

    const int tid = threadIdx.x;
    const int lane = tid & 31;
    const int wid = tid >> 5;
    const int bx = blockIdx.x;
    const int bh = bx & 31;
    const int qslot = bx >> 5;
    const int qb = (31 - qslot) * 64;
    const int b = bh >> 4;
    const int h = bh & 15;

    const __half* qbase = qh + ((size_t)bh * SEQL + qb) * HD;
    const __half* kbase = kh + (size_t)bh * SEQL * HD;
    const __half* vbase = vh + (size_t)bh * SEQL * HD;
    const int* mrow = mask + b * SEQL;
    const int ntiles = qb / 64 + 1;

#pragma unroll
    for (int it = 0; it < 8; it++) {
        int idx = tid + it * 128;
        int row = idx >> 4, u = idx & 15;
        cp_async16(Qs + sw16(row, u), qbase + (size_t)row * HD + u * 8);
    }
    attn_load_tile(KsA[0], VsA[0], kbase, vbase, tid);
    cp_commit();
    if (ntiles > 1) attn_load_tile(KsA[1], VsA[1], kbase + 64 * HD, vbase + 64 * HD, tid);
    cp_commit();

    float oacc[16][4];
#pragma unroll
    for (int i = 0; i < 16; i++) { oacc[i][0] = oacc[i][1] = oacc[i][2] = oacc[i][3] = 0.f; }
    float m0 = -1e30f, m1 = -1e30f, l0 = 0.f, l1 = 0.f;
    const float scale = 0.08838834764831845f;
    const int r = lane >> 2;
    const int c2 = (lane & 3) * 2;
    const int qr0 = qb + wid * 16 + r;
    const unsigned qs_base = smem_addr(Qs);

    for (int t = 0; t < ntiles; t++) {
        asm volatile("cp.async.wait_group 1;\n");
        __syncthreads();
        const int kb = t * 64;
        const unsigned k_base = smem_addr(KsA[t & 1]);
        const unsigned v_base = smem_addr(VsA[t & 1]);

        float sacc[8][4];
#pragma unroll
        for (int nt = 0; nt < 8; nt++) { sacc[nt][0] = sacc[nt][1] = sacc[nt][2] = sacc[nt][3] = 0.f; }
#pragma unroll
        for (int kc = 0; kc < 8; kc++) {
            const int u = kc * 2 + (lane >> 4);
            unsigned afrag[4];
            ldm4(afrag, qs_base + (unsigned)sw16(wid * 16 + (lane & 15), u) * 2);
#pragma unroll
            for (int np = 0; np < 4; np++) {
                unsigned rr[4];
                ldm4(rr, k_base + (unsigned)sw16(np * 16 + (lane & 15), u) * 2);
                mma16816h(sacc[np * 2 + 0], afrag, rr[0], rr[2]);
                mma16816h(sacc[np * 2 + 1], afrag, rr[1], rr[3]);
            }
        }

        float mx0 = -1e30f, mx1 = -1e30f;
#pragma unroll
        for (int nt = 0; nt < 8; nt++) {
#pragma unroll
            for (int i = 0; i < 4; i++) {
                int col = kb + nt * 8 + c2 + (i & 1);
                int qr = qr0 + ((i >> 1) << 3);
                float s = sacc[nt][i] * scale;
                bool dead = (col > qr) || (mrow[col] == 0);
                s = dead ? -10000.f : fmaxf(s, -10000.f);
                sacc[nt][i] = s;
                if (i < 2) mx0 = fmaxf(mx0, s); else mx1 = fmaxf(mx1, s);
            }
        }
        mx0 = fmaxf(mx0, __shfl_xor_sync(0xffffffffu, mx0, 1));
        mx0 = fmaxf(mx0, __shfl_xor_sync(0xffffffffu, mx0, 2));
        mx1 = fmaxf(mx1, __shfl_xor_sync(0xffffffffu, mx1, 1));
        mx1 = fmaxf(mx1, __shfl_xor_sync(0xffffffffu, mx1, 2));
        float nm0 = fmaxf(m0, mx0), nm1 = fmaxf(m1, mx1);
        float cor0 = __expf(m0 - nm0), cor1 = __expf(m1 - nm1);
        float ls0 = 0.f, ls1 = 0.f;
#pragma unroll
        for (int nt = 0; nt < 8; nt++) {
#pragma unroll
            for (int i = 0; i < 4; i++) {
                float p = __expf(sacc[nt][i] - ((i < 2) ? nm0 : nm1));
                sacc[nt][i] = p;
                if (i < 2) ls0 += p; else ls1 += p;
            }
        }
        ls0 += __shfl_xor_sync(0xffffffffu, ls0, 1);
        ls0 += __shfl_xor_sync(0xffffffffu, ls0, 2);
        ls1 += __shfl_xor_sync(0xffffffffu, ls1, 1);
        ls1 += __shfl_xor_sync(0xffffffffu, ls1, 2);
        l0 = l0 * cor0 + ls0;
        l1 = l1 * cor1 + ls1;
        m0 = nm0; m1 = nm1;
#pragma unroll
        for (int i = 0; i < 16; i++) {
            oacc[i][0] *= cor0; oacc[i][1] *= cor0;
            oacc[i][2] *= cor1; oacc[i][3] *= cor1;
        }

#pragma unroll
        for (int kc2 = 0; kc2 < 4; kc2++) {
            unsigned pa[4];
            pa[0] = packh2(sacc[2 * kc2][0], sacc[2 * kc2][1]);
            pa[1] = packh2(sacc[2 * kc2][2], sacc[2 * kc2][3]);
            pa[2] = packh2(sacc[2 * kc2 + 1][0], sacc[2 * kc2 + 1][1]);
            pa[3] = packh2(sacc[2 * kc2 + 1][2], sacc[2 * kc2 + 1][3]);
#pragma unroll
            for (int dnp = 0; dnp < 8; dnp++) {
                unsigned rr[4];
                ldm4t(rr, v_base + (unsigned)sw16(kc2 * 16 + (lane & 15), dnp * 2 + (lane >> 4)) * 2);
                mma16816h(oacc[dnp * 2 + 0], pa, rr[0], rr[1]);
                mma16816h(oacc[dnp * 2 + 1], pa, rr[2], rr[3]);
            }
        }
        __syncthreads();
        if (t + 2 < ntiles)
            attn_load_tile(KsA[t & 1], VsA[t & 1], kbase + (size_t)(t + 2) * 64 * HD,
                           vbase + (size_t)(t + 2) * 64 * HD, tid);
        cp_commit();
    }

    float inv0 = 1.f / l0, inv1 = 1.f / l1;
    size_t o0 = ((size_t)b * SEQL + qr0) * HID + h * HD;
    size_t o1 = o0 + 8 * HID;
#pragma unroll
    for (int dnt = 0; dnt < 16; dnt++) {
        int d = dnt * 8 + c2;
        *(__half2*)(out + o0 + d) = __floats2half2_rn(oacc[dnt][0] * inv0, oacc[dnt][1] * inv0);
        *(__half2*)(out + o1 + d) = __floats2half2_rn(oacc[dnt][2] * inv1, oacc[dnt][3] * inv1);
    }
}

// ------------------------- host orchestration -------------------------
extern "C" void kernel_launch(void* const* d_in, const int* in_sizes, int n_in,
                              void* d_out, int out_size) {
    const float* x     = (const float*)d_in[0];
    const int*   amask = (const int*)d_in[1];
    const float* wq = (const float*)d_in[2];   const float* aq_a = (const float*)d_in[3];
    const float* wk = (const float*)d_in[4];   const float* ak_a = (const float*)d_in[5];
    const float* wv = (const float*)d_in[6];   const float* av_a = (const float*)d_in[7];
    const float* wo = (const float*)d_in[8];   const float* ao_a = (const float*)d_in[9];
    const float* wg = (const float*)d_in[10];  const float* ag_a = (const float*)d_in[11];
    const float* wu = (const float*)d_in[12];  const float* au_a = (const float*)d_in[13];
    const float* wd = (const float*)d_in[14];  const float* ad_a = (const float*)d_in[15];
    const float* n1 = (const float*)d_in[16];
    const float* n2 = (const float*)d_in[17];
    float* out = (float*)d_out;

    __nv_bfloat16 *p_wqkv, *p_wo, *p_wgu, *p_wd, *p_aq;
    __half *p_qh, *p_kh, *p_vh, *p_guh, *p_attnoh;
    float *p_sqkv, *p_so, *p_sgu, *p_sd;
    float *p_as, *p_x1;
    cudaGetSymbolAddress((void**)&p_wqkv, g_wqkv);
    cudaGetSymbolAddress((void**)&p_wo, g_wo);
    cudaGetSymbolAddress((void**)&p_wgu, g_wgu);
    cudaGetSymbolAddress((void**)&p_wd, g_wd);
    cudaGetSymbolAddress((void**)&p_sqkv, g_sqkv);
    cudaGetSymbolAddress((void**)&p_so, g_so);
    cudaGetSymbolAddress((void**)&p_sgu, g_sgu);
    cudaGetSymbolAddress((void**)&p_sd, g_sd);
    cudaGetSymbolAddress((void**)&p_aq, g_aq);
    cudaGetSymbolAddress((void**)&p_as, g_as);
    cudaGetSymbolAddress((void**)&p_qh, g_qh);
    cudaGetSymbolAddress((void**)&p_kh, g_kh);
    cudaGetSymbolAddress((void**)&p_vh, g_vh);
    cudaGetSymbolAddress((void**)&p_attnoh, g_attnoh);
    cudaGetSymbolAddress((void**)&p_x1, g_x1);
    cudaGetSymbolAddress((void**)&p_guh, g_guh);

    const int smem_bytes = 2 * (BM * BK + BN * BK) * 2;   // 65536
    cudaFuncSetAttribute(gemm_bf16_kernel<1>, cudaFuncAttributeMaxDynamicSharedMemorySize, smem_bytes);
    cudaFuncSetAttribute(gemm_bf16_kernel<2>, cudaFuncAttributeMaxDynamicSharedMemorySize, smem_bytes);
    cudaFuncSetAttribute(gemm_bf16_kernel<3>, cudaFuncAttributeMaxDynamicSharedMemorySize, smem_bytes);
    const int attn_smem = 40960 * 2;                      // 81920
    cudaFuncSetAttribute(attn_mma_kernel, cudaFuncAttributeMaxDynamicSharedMemorySize, attn_smem);

    // 1) fused weight quantization (one launch for all 7 matrices)
    QW7 qa;
    qa.W[0] = wq; qa.al[0] = aq_a; qa.out[0] = p_wqkv;                         qa.rs[0] = p_sqkv;           qa.K[0] = HID;
    qa.W[1] = wk; qa.al[1] = ak_a; qa.out[1] = p_wqkv + (size_t)HID * HID;     qa.rs[1] = p_sqkv + HID;     qa.K[1] = HID;
    qa.W[2] = wv; qa.al[2] = av_a; qa.out[2] = p_wqkv + 2 * (size_t)HID * HID; qa.rs[2] = p_sqkv + 2 * HID; qa.K[2] = HID;
    qa.W[3] = wo; qa.al[3] = ao_a; qa.out[3] = p_wo;                           qa.rs[3] = p_so;             qa.K[3] = HID;
    qa.W[4] = wg; qa.al[4] = ag_a; qa.out[4] = p_wgu;                          qa.rs[4] = p_sgu;            qa.K[4] = HID;
    qa.W[5] = wu; qa.al[5] = au_a; qa.out[5] = p_wgu + (size_t)MLPD * HID;     qa.rs[5] = p_sgu + MLPD;     qa.K[5] = HID;
    qa.W[6] = wd; qa.al[6] = ad_a; qa.out[6] = p_wd;                           qa.rs[6] = p_sd;             qa.K[6] = MLPD;
    qa.start[0] = 0;      qa.start[1] = 2048;  qa.start[2] = 4096;  qa.start[3] = 6144;
    qa.start[4] = 8192;   qa.start[5] = 16384; qa.start[6] = 24576;
    quant_w_all_kernel<<<26624, 256>>>(qa);

    // 2) rmsnorm + quantize input
    rms_quant_kernel<<<NTOK, 256>>>(x, n1, p_aq, p_as);

    // 3) fused QKV projection -> fp16 [B,H,S,D]
    dim3 gqkv(3 * HID / BN, NTOK / BM);
    gemm_bf16_kernel<2><<<gqkv, 256, smem_bytes>>>(p_aq, p_wqkv, p_sqkv, p_as,
                                                   p_qh, p_kh, p_vh, nullptr, HID, HID);

    // 4) in-place rope on q,k
    rope_inplace_kernel<<<(NTOK * NH * 64 + 255) / 256, 256>>>(p_qh, p_kh);

    // 5) mma flash attention (fp16 out)
    attn_mma_kernel<<<(SEQL / 64) * 32, 128, attn_smem>>>(p_qh, p_kh, p_vh, amask, p_attnoh);

    // 6) output projection with fused residual: x1 = x + attno @ wo
    act_quant_h_kernel<<<NTOK, 256>>>(p_attnoh, p_aq, p_as);
    dim3 g16(HID / BN, NTOK / BM);
    gemm_bf16_kernel<3><<<g16, 256, smem_bytes>>>(p_aq, p_wo, p_so, p_as,
                                                  p_x1, nullptr, nullptr, x, HID, HID);

    // 7) rmsnorm + quant of x1
    rms_quant_kernel<<<NTOK, 256>>>(p_x1, n2, p_aq, p_as);

    // 8) MLP: fused gate|up GEMM -> fp16, silu+quant, down GEMM with residual into d_out
    dim3 ggu(2 * MLPD / BN, NTOK / BM);
    gemm_bf16_kernel<1><<<ggu, 256, smem_bytes>>>(p_aq, p_wgu, p_sgu, p_as,
                                                  p_guh, nullptr, nullptr, nullptr, HID, 2 * MLPD);
    silu_quant_kernel<<<NTOK, 512>>>(p_guh, p_aq, p_as);
    gemm_bf16_kernel<3><<<g16, 256, smem_bytes>>>(p_aq, p_wd, p_sd, p_as,
                                                  out, nullptr, nullptr, p_x1, MLPD, HID);
    (void)in_sizes; (void)n_in; (void)out_size;
}